// round 4
// baseline (speedup 1.0000x reference)
#include <cuda_runtime.h>
#include <math.h>

#define S_LEN 2048
#define HID_DIM 4096
#define NH 32
#define NKV 8
#define HD 128

// ---------------- scratch (device globals; no allocation allowed) ----------
__device__ float g_Q[(size_t)S_LEN * NH * HD];      // 2048 x 4096
__device__ float g_K[(size_t)S_LEN * NKV * HD];     // 2048 x 1024
__device__ float g_V[(size_t)S_LEN * NKV * HD];     // 2048 x 1024
__device__ float g_attn[(size_t)S_LEN * NH * HD];   // 2048 x 4096
__device__ float g_m[NH * S_LEN];
__device__ float g_l[NH * S_LEN];

// ---------------- classic 128x128x8 SGEMM, 256 threads, 8x8 microtile ------
__global__ __launch_bounds__(256) void sgemm128(const float* __restrict__ A,
                                                const float* __restrict__ B,
                                                float* __restrict__ C,
                                                int M, int N, int K) {
    __shared__ float As[8][128];
    __shared__ float Bs[8][128];
    const int tid = threadIdx.x;
    const int tx = tid & 15, ty = tid >> 4;
    const int arow = tid >> 1, acol = (tid & 1) * 4;
    const int brow = tid >> 5, bcol = (tid & 31) * 4;
    const float* Ap = A + (size_t)(blockIdx.y * 128 + arow) * K + acol;
    const float* Bp = B + (size_t)brow * N + blockIdx.x * 128 + bcol;

    float acc[8][8];
#pragma unroll
    for (int i = 0; i < 8; i++)
#pragma unroll
        for (int j = 0; j < 8; j++) acc[i][j] = 0.f;

    for (int k0 = 0; k0 < K; k0 += 8) {
        float4 a4 = *(const float4*)(Ap + k0);
        float4 b4 = *(const float4*)(Bp + (size_t)k0 * N);
        As[acol + 0][arow] = a4.x;
        As[acol + 1][arow] = a4.y;
        As[acol + 2][arow] = a4.z;
        As[acol + 3][arow] = a4.w;
        *(float4*)&Bs[brow][bcol] = b4;
        __syncthreads();
#pragma unroll
        for (int kk = 0; kk < 8; kk++) {
            float a[8], b[8];
            *(float4*)(a)     = *(const float4*)&As[kk][ty * 8];
            *(float4*)(a + 4) = *(const float4*)&As[kk][ty * 8 + 4];
            *(float4*)(b)     = *(const float4*)&Bs[kk][tx * 8];
            *(float4*)(b + 4) = *(const float4*)&Bs[kk][tx * 8 + 4];
#pragma unroll
            for (int i = 0; i < 8; i++)
#pragma unroll
                for (int j = 0; j < 8; j++) acc[i][j] += a[i] * b[j];
        }
        __syncthreads();
    }
#pragma unroll
    for (int i = 0; i < 8; i++) {
        float* Cp = C + (size_t)(blockIdx.y * 128 + ty * 8 + i) * N + blockIdx.x * 128 + tx * 8;
        *(float4*)Cp       = make_float4(acc[i][0], acc[i][1], acc[i][2], acc[i][3]);
        *(float4*)(Cp + 4) = make_float4(acc[i][4], acc[i][5], acc[i][6], acc[i][7]);
    }
}

// ---------------- RoPE (interleaved pairs) + L2 norm, one (token, head) per block
__global__ __launch_bounds__(64) void rope_norm(const int* __restrict__ pos_ids) {
    const int t = blockIdx.x;
    const int hy = blockIdx.y;  // 0..31 -> Q head, 32..39 -> K head
    float* X;
    if (hy < NH) X = g_Q + (size_t)t * HID_DIM + hy * HD;
    else         X = g_K + (size_t)t * (NKV * HD) + (hy - NH) * HD;

    const int p = threadIdx.x;  // pair index 0..63
    float x0 = X[2 * p], x1 = X[2 * p + 1];
    float pos = (float)pos_ids[t];
    float inv = powf(500000.0f, -((float)(2 * p)) / 128.0f);
    float f = pos * inv;
    float c, s;
    c = cosf(f);
    s = sinf(f);
    float o0 = x0 * c - x1 * s;
    float o1 = x0 * s + x1 * c;

    float ss = o0 * o0 + o1 * o1;
#pragma unroll
    for (int m = 16; m >= 1; m >>= 1) ss += __shfl_xor_sync(0xffffffffu, ss, m);
    __shared__ float sh[2];
    if ((threadIdx.x & 31) == 0) sh[threadIdx.x >> 5] = ss;
    __syncthreads();
    float tot = sh[0] + sh[1];
    float r = rsqrtf(tot / 128.0f + 1e-6f);
    X[2 * p]     = o0 * r;
    X[2 * p + 1] = o1 * r;
}

// ---------------- Attention pass 1: flash-style O + raw score dump --------
// Block = (q-tile of 64 rows, head). 256 threads: tx = tid&15, ty = tid>>4.
// S fragment: rows ty*4+r, cols c*16+tx.  O fragment: rows ty*4+r, cols tx*8+j.
#define QS_STRIDE 132
#define PS_STRIDE 68
__global__ __launch_bounds__(256) void attn_pass1(float* __restrict__ wptr) {
    extern __shared__ float sm[];
    float* Qs = sm;                    // 64 x 132
    float* Ks = sm + 64 * QS_STRIDE;   // 64 x 132
    float* Vs = sm + 2 * 64 * QS_STRIDE;
    float* Ps = sm + 3 * 64 * QS_STRIDE;  // 64 x 68

    const int tid = threadIdx.x;
    const int tx = tid & 15, ty = tid >> 4;
    const int qt = blockIdx.x, h = blockIdx.y;
    const int q0 = qt * 64;
    const int kh = h >> 2;  // GQA: 4 query heads per kv head
    const float scale = 0.08838834764831845f;  // 1/sqrt(128)

    // load Q tile
    for (int idx = tid; idx < 64 * 32; idx += 256) {
        int row = idx >> 5, c4 = (idx & 31) << 2;
        *(float4*)&Qs[row * QS_STRIDE + c4] =
            *(const float4*)&g_Q[(size_t)(q0 + row) * HID_DIM + h * HD + c4];
    }

    float O[4][8];
    float mrow[4], lrow[4];
#pragma unroll
    for (int r = 0; r < 4; r++) {
        mrow[r] = -INFINITY;
        lrow[r] = 0.f;
#pragma unroll
        for (int j = 0; j < 8; j++) O[r][j] = 0.f;
    }

    for (int kt = 0; kt <= qt; kt++) {
        const int k0 = kt * 64;
        for (int idx = tid; idx < 64 * 32; idx += 256) {
            int row = idx >> 5, c4 = (idx & 31) << 2;
            *(float4*)&Ks[row * QS_STRIDE + c4] =
                *(const float4*)&g_K[(size_t)(k0 + row) * (NKV * HD) + kh * HD + c4];
            *(float4*)&Vs[row * QS_STRIDE + c4] =
                *(const float4*)&g_V[(size_t)(k0 + row) * (NKV * HD) + kh * HD + c4];
        }
        __syncthreads();

        // S = Q K^T
        float s[4][4];
#pragma unroll
        for (int r = 0; r < 4; r++)
#pragma unroll
            for (int c = 0; c < 4; c++) s[r][c] = 0.f;

#pragma unroll 8
        for (int k4 = 0; k4 < 32; k4++) {
            float4 qf[4], kf[4];
#pragma unroll
            for (int r = 0; r < 4; r++)
                qf[r] = *(const float4*)&Qs[(ty * 4 + r) * QS_STRIDE + k4 * 4];
#pragma unroll
            for (int c = 0; c < 4; c++)
                kf[c] = *(const float4*)&Ks[(c * 16 + tx) * QS_STRIDE + k4 * 4];
#pragma unroll
            for (int r = 0; r < 4; r++)
#pragma unroll
                for (int c = 0; c < 4; c++) {
                    s[r][c] += qf[r].x * kf[c].x + qf[r].y * kf[c].y +
                               qf[r].z * kf[c].z + qf[r].w * kf[c].w;
                }
        }

        const bool diag = (kt == qt);
#pragma unroll
        for (int r = 0; r < 4; r++) {
            int i = q0 + ty * 4 + r;
#pragma unroll
            for (int c = 0; c < 4; c++) {
                s[r][c] *= scale;
                if (diag && (k0 + c * 16 + tx) > i) s[r][c] += -1e9f;
            }
        }

        // dump raw (scaled+masked) scores for pass 2
        if (wptr) {
#pragma unroll
            for (int r = 0; r < 4; r++) {
                size_t base = ((size_t)h * S_LEN + (q0 + ty * 4 + r)) * S_LEN + k0;
#pragma unroll
                for (int c = 0; c < 4; c++) wptr[base + c * 16 + tx] = s[r][c];
            }
        }

        // online softmax update
#pragma unroll
        for (int r = 0; r < 4; r++) {
            float rm = fmaxf(fmaxf(s[r][0], s[r][1]), fmaxf(s[r][2], s[r][3]));
#pragma unroll
            for (int off = 8; off >= 1; off >>= 1)
                rm = fmaxf(rm, __shfl_xor_sync(0xffffffffu, rm, off));
            float mn = fmaxf(mrow[r], rm);
            float f = expf(mrow[r] - mn);
            mrow[r] = mn;
            float rs = 0.f;
#pragma unroll
            for (int c = 0; c < 4; c++) {
                float p = expf(s[r][c] - mn);
                Ps[(ty * 4 + r) * PS_STRIDE + c * 16 + tx] = p;
                rs += p;
            }
#pragma unroll
            for (int off = 8; off >= 1; off >>= 1)
                rs += __shfl_xor_sync(0xffffffffu, rs, off);
            lrow[r] = lrow[r] * f + rs;
#pragma unroll
            for (int j = 0; j < 8; j++) O[r][j] *= f;
        }
        __syncthreads();

        // O += P @ V
#pragma unroll 4
        for (int k = 0; k < 64; k++) {
            float pr[4];
#pragma unroll
            for (int r = 0; r < 4; r++) pr[r] = Ps[(ty * 4 + r) * PS_STRIDE + k];
            float4 v0 = *(const float4*)&Vs[k * QS_STRIDE + tx * 8];
            float4 v1 = *(const float4*)&Vs[k * QS_STRIDE + tx * 8 + 4];
#pragma unroll
            for (int r = 0; r < 4; r++) {
                O[r][0] += pr[r] * v0.x;
                O[r][1] += pr[r] * v0.y;
                O[r][2] += pr[r] * v0.z;
                O[r][3] += pr[r] * v0.w;
                O[r][4] += pr[r] * v1.x;
                O[r][5] += pr[r] * v1.y;
                O[r][6] += pr[r] * v1.z;
                O[r][7] += pr[r] * v1.w;
            }
        }
        __syncthreads();
    }

    // epilogue: normalize O, save per-row stats
#pragma unroll
    for (int r = 0; r < 4; r++) {
        float inv = 1.0f / lrow[r];
        size_t base = (size_t)(q0 + ty * 4 + r) * HID_DIM + h * HD + tx * 8;
        *(float4*)&g_attn[base] =
            make_float4(O[r][0] * inv, O[r][1] * inv, O[r][2] * inv, O[r][3] * inv);
        *(float4*)&g_attn[base + 4] =
            make_float4(O[r][4] * inv, O[r][5] * inv, O[r][6] * inv, O[r][7] * inv);
        if (tx == 0) {
            g_m[h * S_LEN + q0 + ty * 4 + r] = mrow[r];
            g_l[h * S_LEN + q0 + ty * 4 + r] = lrow[r];
        }
    }
}

// ---------------- Attention pass 2: normalize scores -> weights -----------
__global__ __launch_bounds__(256) void softmax_norm(float* __restrict__ w) {
    size_t t = (size_t)blockIdx.x * 256 + threadIdx.x;
    size_t e = t * 4;  // element offset; total 32*2048*2048
    int h = (int)(e >> 22);
    int i = (int)((e >> 11) & 2047);
    int j = (int)(e & 2047);
    float4* p = (float4*)(w + e);
    if (j > i) {  // fully masked block (includes never-written tiles)
        *p = make_float4(0.f, 0.f, 0.f, 0.f);
        return;
    }
    float m = g_m[h * S_LEN + i];
    float inv = 1.0f / g_l[h * S_LEN + i];
    float4 s4 = *p;
    float4 o;
    o.x = expf(s4.x - m) * inv;
    o.y = (j + 1 <= i) ? expf(s4.y - m) * inv : 0.f;
    o.z = (j + 2 <= i) ? expf(s4.z - m) * inv : 0.f;
    o.w = (j + 3 <= i) ? expf(s4.w - m) * inv : 0.f;
    *p = o;
}

// ---------------- launcher --------------------------------------------------
extern "C" void kernel_launch(void* const* d_in, const int* in_sizes, int n_in,
                              void* d_out, int out_size) {
    const float* hidden = (const float*)d_in[0];
    // d_in[1] = attention_mask: exact causal mask, implemented analytically
    const int* pos = (const int*)d_in[2];
    const float* Wq = (const float*)d_in[3];
    const float* Wk = (const float*)d_in[4];
    const float* Wv = (const float*)d_in[5];
    const float* Wo = (const float*)d_in[6];

    float *qp, *kp, *vp, *ap;
    cudaGetSymbolAddress((void**)&qp, g_Q);
    cudaGetSymbolAddress((void**)&kp, g_K);
    cudaGetSymbolAddress((void**)&vp, g_V);
    cudaGetSymbolAddress((void**)&ap, g_attn);

    float* out = (float*)d_out;
    const long long ATTN_N = (long long)S_LEN * HID_DIM;            // 8388608
    const long long WEI_N = (long long)NH * S_LEN * S_LEN;          // 134217728
    float* obase = nullptr;
    float* wbase = nullptr;
    long long osz = (long long)out_size;
    if (osz >= ATTN_N + WEI_N) { obase = out; wbase = out + ATTN_N; }
    else if (osz == WEI_N)     { wbase = out; }
    else                       { obase = out; }

    // projections
    sgemm128<<<dim3(32, 16), 256>>>(hidden, Wq, qp, S_LEN, HID_DIM, HID_DIM);
    sgemm128<<<dim3(8, 16),  256>>>(hidden, Wk, kp, S_LEN, NKV * HD, HID_DIM);
    sgemm128<<<dim3(8, 16),  256>>>(hidden, Wv, vp, S_LEN, NKV * HD, HID_DIM);

    // rope + l2norm (Q: heads 0..31, K: heads 32..39)
    rope_norm<<<dim3(S_LEN, NH + NKV), 64>>>(pos);

    // attention
    static const int smem_bytes = (3 * 64 * QS_STRIDE + 64 * PS_STRIDE) * 4;  // 118784
    cudaFuncSetAttribute(attn_pass1, cudaFuncAttributeMaxDynamicSharedMemorySize, smem_bytes);
    attn_pass1<<<dim3(S_LEN / 64, NH), 256, smem_bytes>>>(wbase);

    if (wbase) softmax_norm<<<(unsigned)(WEI_N / 4 / 256), 256>>>(wbase);

    // output projection
    if (obase) sgemm128<<<dim3(32, 16), 256>>>(ap, Wo, obase, S_LEN, HID_DIM, HID_DIM);
}

// round 8
// speedup vs baseline: 1.8606x; 1.8606x over previous
#include <cuda_runtime.h>
#include <cuda_bf16.h>
#include <math.h>
#include <stdint.h>

#define S_LEN 2048
#define HID_DIM 4096
#define NH 32
#define NKV 8
#define HD 128

// ---------------- scratch (device globals; no allocation allowed) ----------
__device__ float g_Q[(size_t)S_LEN * NH * HD];
__device__ float g_K[(size_t)S_LEN * NKV * HD];
__device__ float g_V[(size_t)S_LEN * NKV * HD];
__device__ float g_attn[(size_t)S_LEN * NH * HD];
__device__ float g_m[NH * S_LEN];
__device__ float g_l[NH * S_LEN];

// bf16 split buffers
__device__ __nv_bfloat16 g_Ah[(size_t)S_LEN * HID_DIM];
__device__ __nv_bfloat16 g_Al[(size_t)S_LEN * HID_DIM];
__device__ __nv_bfloat16 g_WqTh[(size_t)HID_DIM * HID_DIM];   // [N][K]
__device__ __nv_bfloat16 g_WqTl[(size_t)HID_DIM * HID_DIM];
__device__ __nv_bfloat16 g_WkTh[(size_t)(NKV * HD) * HID_DIM];
__device__ __nv_bfloat16 g_WkTl[(size_t)(NKV * HD) * HID_DIM];
__device__ __nv_bfloat16 g_WvTh[(size_t)(NKV * HD) * HID_DIM];
__device__ __nv_bfloat16 g_WvTl[(size_t)(NKV * HD) * HID_DIM];
__device__ __nv_bfloat16 g_WoTh[(size_t)HID_DIM * HID_DIM];
__device__ __nv_bfloat16 g_WoTl[(size_t)HID_DIM * HID_DIM];

// ---------------- PTX helpers (all plain sm_80+ features) ------------------
__device__ __forceinline__ uint32_t smem_u32(const void* p) {
    uint32_t a;
    asm("{ .reg .u64 t; cvta.to.shared.u64 t, %1; cvt.u32.u64 %0, t; }"
        : "=r"(a) : "l"(p));
    return a;
}
__device__ __forceinline__ void cp_async16(uint32_t dst, const void* src) {
    asm volatile("cp.async.cg.shared.global [%0], [%1], 16;" :: "r"(dst), "l"(src));
}
#define CP_COMMIT() asm volatile("cp.async.commit_group;" ::: "memory")
#define CP_WAIT(n)  asm volatile("cp.async.wait_group %0;" :: "n"(n) : "memory")

__device__ __forceinline__ void ldsm4(uint32_t (&r)[4], uint32_t addr) {
    asm volatile("ldmatrix.sync.aligned.m8n8.x4.shared.b16 {%0,%1,%2,%3}, [%4];"
                 : "=r"(r[0]), "=r"(r[1]), "=r"(r[2]), "=r"(r[3]) : "r"(addr));
}
__device__ __forceinline__ void mma16816(float (&c)[4], const uint32_t (&a)[4],
                                         uint32_t b0, uint32_t b1) {
    asm volatile(
        "mma.sync.aligned.m16n8k16.row.col.f32.bf16.bf16.f32 "
        "{%0,%1,%2,%3}, {%4,%5,%6,%7}, {%8,%9}, {%0,%1,%2,%3};"
        : "+f"(c[0]), "+f"(c[1]), "+f"(c[2]), "+f"(c[3])
        : "r"(a[0]), "r"(a[1]), "r"(a[2]), "r"(a[3]), "r"(b0), "r"(b1));
}

// ---------------- prepass: fp32 -> bf16 hi/lo split ------------------------
__global__ __launch_bounds__(256) void convert_split(const float* __restrict__ X,
                                                     __nv_bfloat16* __restrict__ H,
                                                     __nv_bfloat16* __restrict__ L,
                                                     int n4) {
    int idx = blockIdx.x * 256 + threadIdx.x;
    if (idx >= n4) return;
    float4 v = *(const float4*)(X + (size_t)idx * 4);
    __nv_bfloat16 h0 = __float2bfloat16(v.x), h1 = __float2bfloat16(v.y);
    __nv_bfloat16 h2 = __float2bfloat16(v.z), h3 = __float2bfloat16(v.w);
    __nv_bfloat16 l0 = __float2bfloat16(v.x - __bfloat162float(h0));
    __nv_bfloat16 l1 = __float2bfloat16(v.y - __bfloat162float(h1));
    __nv_bfloat16 l2 = __float2bfloat16(v.z - __bfloat162float(h2));
    __nv_bfloat16 l3 = __float2bfloat16(v.w - __bfloat162float(h3));
    ((__nv_bfloat162*)H)[idx * 2]     = __nv_bfloat162(h0, h1);
    ((__nv_bfloat162*)H)[idx * 2 + 1] = __nv_bfloat162(h2, h3);
    ((__nv_bfloat162*)L)[idx * 2]     = __nv_bfloat162(l0, l1);
    ((__nv_bfloat162*)L)[idx * 2 + 1] = __nv_bfloat162(l2, l3);
}

// W[K][N] fp32 -> Th/Tl[N][K] bf16 (transpose + split)
__global__ __launch_bounds__(256) void transpose_split(const float* __restrict__ W,
                                                       __nv_bfloat16* __restrict__ Th,
                                                       __nv_bfloat16* __restrict__ Tl,
                                                       int K, int N) {
    __shared__ float t[32][33];
    int n = blockIdx.x * 32 + threadIdx.x;
    int k0 = blockIdx.y * 32;
    for (int j = threadIdx.y; j < 32; j += 8)
        t[j][threadIdx.x] = W[(size_t)(k0 + j) * N + n];
    __syncthreads();
    int k = k0 + threadIdx.x;
    for (int j = threadIdx.y; j < 32; j += 8) {
        int nn = blockIdx.x * 32 + j;
        float v = t[threadIdx.x][j];
        __nv_bfloat16 h = __float2bfloat16(v);
        Th[(size_t)nn * K + k] = h;
        Tl[(size_t)nn * K + k] = __float2bfloat16(v - __bfloat162float(h));
    }
}

// ---------------- mma.sync bf16x3 GEMM: C[M,N] = A[M,K] * Bt[N,K]^T --------
// 128x128x32 CTA tile, 8 warps (2m x 4n), warp tile 64x32, double-buffered.
#define BK 32
#define AST 40                          // smem row stride (halves)
#define MAT_BYTES (128 * AST * 2)       // 10240
#define STAGE_BYTES (4 * MAT_BYTES)     // 40960
#define GEMM_SMEM (2 * STAGE_BYTES)     // 81920

__global__ __launch_bounds__(256)
void gemm_bf16x3(const __nv_bfloat16* __restrict__ Ah, const __nv_bfloat16* __restrict__ Al,
                 const __nv_bfloat16* __restrict__ Bh, const __nv_bfloat16* __restrict__ Bl,
                 float* __restrict__ C, int N, int K) {
    extern __shared__ char smc[];
    const uint32_t sb = smem_u32(smc);
    const int tid = threadIdx.x, lane = tid & 31, wid = tid >> 5;
    const int wm = wid & 1, wn = wid >> 1;
    const int m0 = blockIdx.y * 128, n0 = blockIdx.x * 128;
    const __nv_bfloat16* gsrc[4] = { Ah + (size_t)m0 * K, Al + (size_t)m0 * K,
                                     Bh + (size_t)n0 * K, Bl + (size_t)n0 * K };
    const int lrow = tid >> 2, lq = tid & 3;
    const int nch = K / BK;

    float acc[4][4][4];
#pragma unroll
    for (int i = 0; i < 4; i++)
#pragma unroll
        for (int j = 0; j < 4; j++)
#pragma unroll
            for (int q = 0; q < 4; q++) acc[i][j][q] = 0.f;

    // prologue: stage 0 <- chunk 0
#pragma unroll
    for (int a = 0; a < 4; a++)
#pragma unroll
        for (int it = 0; it < 2; it++) {
            int r = lrow + it * 64;
            cp_async16(sb + a * MAT_BYTES + (r * AST + lq * 8) * 2,
                       gsrc[a] + (size_t)r * K + lq * 8);
        }
    CP_COMMIT();

    for (int c = 0; c < nch; c++) {
        const int s = c & 1;
        if (c + 1 < nch) {
            uint32_t d0 = sb + (s ^ 1) * STAGE_BYTES;
#pragma unroll
            for (int a = 0; a < 4; a++)
#pragma unroll
                for (int it = 0; it < 2; it++) {
                    int r = lrow + it * 64;
                    cp_async16(d0 + a * MAT_BYTES + (r * AST + lq * 8) * 2,
                               gsrc[a] + (size_t)r * K + (c + 1) * BK + lq * 8);
                }
            CP_COMMIT();
            CP_WAIT(1);
        } else {
            CP_WAIT(0);
        }
        __syncthreads();

        const uint32_t base = sb + s * STAGE_BYTES;
        const int arow = wm * 64 + (lane & 7) + ((lane >> 3) & 1) * 8;
        const int brow = wn * 32 + (lane & 7) + ((lane >> 4) & 1) * 8;
#pragma unroll
        for (int ks = 0; ks < 2; ks++) {
            const int acol = ks * 16 + ((lane >> 4) & 1) * 8;
            const int bcol = ks * 16 + ((lane >> 3) & 1) * 8;
            uint32_t ah[4][4], alr[4][4], bh[2][4], blr[2][4];
#pragma unroll
            for (int mt = 0; mt < 4; mt++) {
                uint32_t ad = base + ((arow + mt * 16) * AST + acol) * 2;
                ldsm4(ah[mt], ad);
                ldsm4(alr[mt], ad + MAT_BYTES);
            }
#pragma unroll
            for (int np = 0; np < 2; np++) {
                uint32_t bd = base + 2 * MAT_BYTES + ((brow + np * 16) * AST + bcol) * 2;
                ldsm4(bh[np], bd);
                ldsm4(blr[np], bd + MAT_BYTES);
            }
#pragma unroll
            for (int mt = 0; mt < 4; mt++)
#pragma unroll
                for (int nt = 0; nt < 4; nt++) {
                    const int np = nt >> 1, off = (nt & 1) * 2;
                    mma16816(acc[mt][nt], ah[mt], bh[np][off], bh[np][off + 1]);
                    mma16816(acc[mt][nt], ah[mt], blr[np][off], blr[np][off + 1]);
                    mma16816(acc[mt][nt], alr[mt], bh[np][off], bh[np][off + 1]);
                }
        }
        __syncthreads();
    }

    // epilogue: direct fp32 stores
    const int g = lane >> 2, tg = lane & 3;
#pragma unroll
    for (int mt = 0; mt < 4; mt++)
#pragma unroll
        for (int nt = 0; nt < 4; nt++) {
            int gr = m0 + wm * 64 + mt * 16 + g;
            int gc = n0 + wn * 32 + nt * 8 + tg * 2;
            *(float2*)&C[(size_t)gr * N + gc] = make_float2(acc[mt][nt][0], acc[mt][nt][1]);
            *(float2*)&C[(size_t)(gr + 8) * N + gc] = make_float2(acc[mt][nt][2], acc[mt][nt][3]);
        }
}

// ---------------- RoPE (interleaved pairs) + L2 norm -----------------------
__global__ __launch_bounds__(64) void rope_norm(const int* __restrict__ pos_ids) {
    const int t = blockIdx.x;
    const int hy = blockIdx.y;
    float* X;
    if (hy < NH) X = g_Q + (size_t)t * HID_DIM + hy * HD;
    else         X = g_K + (size_t)t * (NKV * HD) + (hy - NH) * HD;

    const int p = threadIdx.x;
    float x0 = X[2 * p], x1 = X[2 * p + 1];
    float pos = (float)pos_ids[t];
    float inv = powf(500000.0f, -((float)(2 * p)) / 128.0f);
    float f = pos * inv;
    float c = cosf(f), s = sinf(f);
    float o0 = x0 * c - x1 * s;
    float o1 = x0 * s + x1 * c;

    float ss = o0 * o0 + o1 * o1;
#pragma unroll
    for (int m = 16; m >= 1; m >>= 1) ss += __shfl_xor_sync(0xffffffffu, ss, m);
    __shared__ float sh[2];
    if ((threadIdx.x & 31) == 0) sh[threadIdx.x >> 5] = ss;
    __syncthreads();
    float tot = sh[0] + sh[1];
    float r = rsqrtf(tot / 128.0f + 1e-6f);
    X[2 * p]     = o0 * r;
    X[2 * p + 1] = o1 * r;
}

// ---------------- Attention pass 1: flash-style O + raw score dump --------
#define QS_STRIDE 132
#define PS_STRIDE 68
__global__ __launch_bounds__(256) void attn_pass1(float* __restrict__ wptr) {
    extern __shared__ float sm[];
    float* Qs = sm;
    float* Ks = sm + 64 * QS_STRIDE;
    float* Vs = sm + 2 * 64 * QS_STRIDE;
    float* Ps = sm + 3 * 64 * QS_STRIDE;

    const int tid = threadIdx.x;
    const int tx = tid & 15, ty = tid >> 4;
    const int qt = blockIdx.x, h = blockIdx.y;
    const int q0 = qt * 64;
    const int kh = h >> 2;
    const float scale = 0.08838834764831845f;

    for (int idx = tid; idx < 64 * 32; idx += 256) {
        int row = idx >> 5, c4 = (idx & 31) << 2;
        *(float4*)&Qs[row * QS_STRIDE + c4] =
            *(const float4*)&g_Q[(size_t)(q0 + row) * HID_DIM + h * HD + c4];
    }

    float O[4][8];
    float mrow[4], lrow[4];
#pragma unroll
    for (int r = 0; r < 4; r++) {
        mrow[r] = -INFINITY;
        lrow[r] = 0.f;
#pragma unroll
        for (int j = 0; j < 8; j++) O[r][j] = 0.f;
    }

    for (int kt = 0; kt <= qt; kt++) {
        const int k0 = kt * 64;
        for (int idx = tid; idx < 64 * 32; idx += 256) {
            int row = idx >> 5, c4 = (idx & 31) << 2;
            *(float4*)&Ks[row * QS_STRIDE + c4] =
                *(const float4*)&g_K[(size_t)(k0 + row) * (NKV * HD) + kh * HD + c4];
            *(float4*)&Vs[row * QS_STRIDE + c4] =
                *(const float4*)&g_V[(size_t)(k0 + row) * (NKV * HD) + kh * HD + c4];
        }
        __syncthreads();

        float s[4][4];
#pragma unroll
        for (int r = 0; r < 4; r++)
#pragma unroll
            for (int c = 0; c < 4; c++) s[r][c] = 0.f;

#pragma unroll 8
        for (int k4 = 0; k4 < 32; k4++) {
            float4 qf[4], kf[4];
#pragma unroll
            for (int r = 0; r < 4; r++)
                qf[r] = *(const float4*)&Qs[(ty * 4 + r) * QS_STRIDE + k4 * 4];
#pragma unroll
            for (int c = 0; c < 4; c++)
                kf[c] = *(const float4*)&Ks[(c * 16 + tx) * QS_STRIDE + k4 * 4];
#pragma unroll
            for (int r = 0; r < 4; r++)
#pragma unroll
                for (int c = 0; c < 4; c++) {
                    s[r][c] += qf[r].x * kf[c].x + qf[r].y * kf[c].y +
                               qf[r].z * kf[c].z + qf[r].w * kf[c].w;
                }
        }

        const bool diag = (kt == qt);
#pragma unroll
        for (int r = 0; r < 4; r++) {
            int i = q0 + ty * 4 + r;
#pragma unroll
            for (int c = 0; c < 4; c++) {
                s[r][c] *= scale;
                if (diag && (k0 + c * 16 + tx) > i) s[r][c] += -1e9f;
            }
        }

        if (wptr) {
#pragma unroll
            for (int r = 0; r < 4; r++) {
                size_t base = ((size_t)h * S_LEN + (q0 + ty * 4 + r)) * S_LEN + k0;
#pragma unroll
                for (int c = 0; c < 4; c++) wptr[base + c * 16 + tx] = s[r][c];
            }
        }

#pragma unroll
        for (int r = 0; r < 4; r++) {
            float rm = fmaxf(fmaxf(s[r][0], s[r][1]), fmaxf(s[r][2], s[r][3]));
#pragma unroll
            for (int off = 8; off >= 1; off >>= 1)
                rm = fmaxf(rm, __shfl_xor_sync(0xffffffffu, rm, off));
            float mn = fmaxf(mrow[r], rm);
            float f = expf(mrow[r] - mn);
            mrow[r] = mn;
            float rs = 0.f;
#pragma unroll
            for (int c = 0; c < 4; c++) {
                float p = expf(s[r][c] - mn);
                Ps[(ty * 4 + r) * PS_STRIDE + c * 16 + tx] = p;
                rs += p;
            }
#pragma unroll
            for (int off = 8; off >= 1; off >>= 1)
                rs += __shfl_xor_sync(0xffffffffu, rs, off);
            lrow[r] = lrow[r] * f + rs;
#pragma unroll
            for (int j = 0; j < 8; j++) O[r][j] *= f;
        }
        __syncthreads();

#pragma unroll 4
        for (int k = 0; k < 64; k++) {
            float pr[4];
#pragma unroll
            for (int r = 0; r < 4; r++) pr[r] = Ps[(ty * 4 + r) * PS_STRIDE + k];
            float4 v0 = *(const float4*)&Vs[k * QS_STRIDE + tx * 8];
            float4 v1 = *(const float4*)&Vs[k * QS_STRIDE + tx * 8 + 4];
#pragma unroll
            for (int r = 0; r < 4; r++) {
                O[r][0] += pr[r] * v0.x;
                O[r][1] += pr[r] * v0.y;
                O[r][2] += pr[r] * v0.z;
                O[r][3] += pr[r] * v0.w;
                O[r][4] += pr[r] * v1.x;
                O[r][5] += pr[r] * v1.y;
                O[r][6] += pr[r] * v1.z;
                O[r][7] += pr[r] * v1.w;
            }
        }
        __syncthreads();
    }

#pragma unroll
    for (int r = 0; r < 4; r++) {
        float inv = 1.0f / lrow[r];
        size_t base = (size_t)(q0 + ty * 4 + r) * HID_DIM + h * HD + tx * 8;
        *(float4*)&g_attn[base] =
            make_float4(O[r][0] * inv, O[r][1] * inv, O[r][2] * inv, O[r][3] * inv);
        *(float4*)&g_attn[base + 4] =
            make_float4(O[r][4] * inv, O[r][5] * inv, O[r][6] * inv, O[r][7] * inv);
        if (tx == 0) {
            g_m[h * S_LEN + q0 + ty * 4 + r] = mrow[r];
            g_l[h * S_LEN + q0 + ty * 4 + r] = lrow[r];
        }
    }
}

// ---------------- Attention pass 2: normalize scores -> weights -----------
__global__ __launch_bounds__(256) void softmax_norm(float* __restrict__ w) {
    size_t t = (size_t)blockIdx.x * 256 + threadIdx.x;
    size_t e = t * 4;
    int h = (int)(e >> 22);
    int i = (int)((e >> 11) & 2047);
    int j = (int)(e & 2047);
    float4* p = (float4*)(w + e);
    if (j > i) {
        *p = make_float4(0.f, 0.f, 0.f, 0.f);
        return;
    }
    float m = g_m[h * S_LEN + i];
    float inv = 1.0f / g_l[h * S_LEN + i];
    float4 s4 = *p;
    float4 o;
    o.x = expf(s4.x - m) * inv;
    o.y = (j + 1 <= i) ? expf(s4.y - m) * inv : 0.f;
    o.z = (j + 2 <= i) ? expf(s4.z - m) * inv : 0.f;
    o.w = (j + 3 <= i) ? expf(s4.w - m) * inv : 0.f;
    *p = o;
}

// ---------------- launcher --------------------------------------------------
extern "C" void kernel_launch(void* const* d_in, const int* in_sizes, int n_in,
                              void* d_out, int out_size) {
    const float* hidden = (const float*)d_in[0];
    const int* pos = (const int*)d_in[2];
    const float* Wq = (const float*)d_in[3];
    const float* Wk = (const float*)d_in[4];
    const float* Wv = (const float*)d_in[5];
    const float* Wo = (const float*)d_in[6];

    float *qp, *kp, *vp, *ap;
    cudaGetSymbolAddress((void**)&qp, g_Q);
    cudaGetSymbolAddress((void**)&kp, g_K);
    cudaGetSymbolAddress((void**)&vp, g_V);
    cudaGetSymbolAddress((void**)&ap, g_attn);
    __nv_bfloat16 *ah, *al, *wqh, *wql, *wkh, *wkl, *wvh, *wvl, *woh, *wol;
    cudaGetSymbolAddress((void**)&ah, g_Ah);
    cudaGetSymbolAddress((void**)&al, g_Al);
    cudaGetSymbolAddress((void**)&wqh, g_WqTh);
    cudaGetSymbolAddress((void**)&wql, g_WqTl);
    cudaGetSymbolAddress((void**)&wkh, g_WkTh);
    cudaGetSymbolAddress((void**)&wkl, g_WkTl);
    cudaGetSymbolAddress((void**)&wvh, g_WvTh);
    cudaGetSymbolAddress((void**)&wvl, g_WvTl);
    cudaGetSymbolAddress((void**)&woh, g_WoTh);
    cudaGetSymbolAddress((void**)&wol, g_WoTl);

    float* out = (float*)d_out;
    const long long ATTN_N = (long long)S_LEN * HID_DIM;
    const long long WEI_N = (long long)NH * S_LEN * S_LEN;
    float* obase = nullptr;
    float* wbase = nullptr;
    long long osz = (long long)out_size;
    if (osz >= ATTN_N + WEI_N) { obase = out; wbase = out + ATTN_N; }
    else if (osz == WEI_N)     { wbase = out; }
    else                       { obase = out; }

    cudaFuncSetAttribute(gemm_bf16x3, cudaFuncAttributeMaxDynamicSharedMemorySize, GEMM_SMEM);

    // prepass: split hidden, transpose+split weights
    convert_split<<<(S_LEN * HID_DIM) / 1024, 256>>>(hidden, ah, al, (S_LEN * HID_DIM) / 4);
    transpose_split<<<dim3(HID_DIM / 32, HID_DIM / 32), dim3(32, 8)>>>(Wq, wqh, wql, HID_DIM, HID_DIM);
    transpose_split<<<dim3((NKV * HD) / 32, HID_DIM / 32), dim3(32, 8)>>>(Wk, wkh, wkl, HID_DIM, NKV * HD);
    transpose_split<<<dim3((NKV * HD) / 32, HID_DIM / 32), dim3(32, 8)>>>(Wv, wvh, wvl, HID_DIM, NKV * HD);
    transpose_split<<<dim3(HID_DIM / 32, HID_DIM / 32), dim3(32, 8)>>>(Wo, woh, wol, HID_DIM, HID_DIM);

    // projections on tensor cores (mma.sync bf16x3)
    gemm_bf16x3<<<dim3(32, 16), 256, GEMM_SMEM>>>(ah, al, wqh, wql, qp, HID_DIM, HID_DIM);
    gemm_bf16x3<<<dim3(8, 16),  256, GEMM_SMEM>>>(ah, al, wkh, wkl, kp, NKV * HD, HID_DIM);
    gemm_bf16x3<<<dim3(8, 16),  256, GEMM_SMEM>>>(ah, al, wvh, wvl, vp, NKV * HD, HID_DIM);

    rope_norm<<<dim3(S_LEN, NH + NKV), 64>>>(pos);

    static const int smem_bytes = (3 * 64 * QS_STRIDE + 64 * PS_STRIDE) * 4;
    cudaFuncSetAttribute(attn_pass1, cudaFuncAttributeMaxDynamicSharedMemorySize, smem_bytes);
    attn_pass1<<<dim3(S_LEN / 64, NH), 256, smem_bytes>>>(wbase);

    if (wbase) softmax_norm<<<(unsigned)(WEI_N / 4 / 256), 256>>>(wbase);

    if (obase) {
        convert_split<<<(S_LEN * HID_DIM) / 1024, 256>>>(ap, ah, al, (S_LEN * HID_DIM) / 4);
        gemm_bf16x3<<<dim3(32, 16), 256, GEMM_SMEM>>>(ah, al, woh, wol, obase, HID_DIM, HID_DIM);
    }
}

// round 10
// speedup vs baseline: 2.7251x; 1.4646x over previous
#include <cuda_runtime.h>
#include <cuda_bf16.h>
#include <math.h>
#include <stdint.h>

#define S_LEN 2048
#define HID_DIM 4096
#define NH 32
#define NKV 8
#define HD 128

// ---------------- scratch (device globals; no allocation allowed) ----------
__device__ float g_Q[(size_t)S_LEN * NH * HD];     // fp32 Wq output (rope input)
__device__ float g_K[(size_t)S_LEN * NKV * HD];
__device__ float g_V[(size_t)S_LEN * NKV * HD];
__device__ float g_attn[(size_t)S_LEN * NH * HD];
__device__ float g_m[NH * S_LEN];
__device__ float g_l[NH * S_LEN];

// bf16 split buffers
__device__ __nv_bfloat16 g_Ah[(size_t)S_LEN * HID_DIM];
__device__ __nv_bfloat16 g_Al[(size_t)S_LEN * HID_DIM];
__device__ __nv_bfloat16 g_WqTh[(size_t)HID_DIM * HID_DIM];   // [N][K]
__device__ __nv_bfloat16 g_WqTl[(size_t)HID_DIM * HID_DIM];
__device__ __nv_bfloat16 g_WkTh[(size_t)(NKV * HD) * HID_DIM];
__device__ __nv_bfloat16 g_WkTl[(size_t)(NKV * HD) * HID_DIM];
__device__ __nv_bfloat16 g_WvTh[(size_t)(NKV * HD) * HID_DIM];
__device__ __nv_bfloat16 g_WvTl[(size_t)(NKV * HD) * HID_DIM];
__device__ __nv_bfloat16 g_WoTh[(size_t)HID_DIM * HID_DIM];
__device__ __nv_bfloat16 g_WoTl[(size_t)HID_DIM * HID_DIM];
// post-rope bf16 splits for attention
__device__ __nv_bfloat16 g_Qh[(size_t)S_LEN * NH * HD];
__device__ __nv_bfloat16 g_Ql[(size_t)S_LEN * NH * HD];
__device__ __nv_bfloat16 g_Kh[(size_t)S_LEN * NKV * HD];
__device__ __nv_bfloat16 g_Kl[(size_t)S_LEN * NKV * HD];
__device__ __nv_bfloat16 g_Vh[(size_t)S_LEN * NKV * HD];
__device__ __nv_bfloat16 g_Vl[(size_t)S_LEN * NKV * HD];

// ---------------- PTX helpers (plain sm_80+ features only) -----------------
__device__ __forceinline__ uint32_t smem_u32(const void* p) {
    uint32_t a;
    asm("{ .reg .u64 t; cvta.to.shared.u64 t, %1; cvt.u32.u64 %0, t; }"
        : "=r"(a) : "l"(p));
    return a;
}
__device__ __forceinline__ void cp_async16(uint32_t dst, const void* src) {
    asm volatile("cp.async.cg.shared.global [%0], [%1], 16;" :: "r"(dst), "l"(src));
}
#define CP_COMMIT() asm volatile("cp.async.commit_group;" ::: "memory")
#define CP_WAIT(n)  asm volatile("cp.async.wait_group %0;" :: "n"(n) : "memory")

__device__ __forceinline__ void ldsm4(uint32_t (&r)[4], uint32_t addr) {
    asm volatile("ldmatrix.sync.aligned.m8n8.x4.shared.b16 {%0,%1,%2,%3}, [%4];"
                 : "=r"(r[0]), "=r"(r[1]), "=r"(r[2]), "=r"(r[3]) : "r"(addr));
}
__device__ __forceinline__ void ldsm4t(uint32_t (&r)[4], uint32_t addr) {
    asm volatile("ldmatrix.sync.aligned.m8n8.x4.trans.shared.b16 {%0,%1,%2,%3}, [%4];"
                 : "=r"(r[0]), "=r"(r[1]), "=r"(r[2]), "=r"(r[3]) : "r"(addr));
}
__device__ __forceinline__ void mma16816(float (&c)[4], const uint32_t (&a)[4],
                                         uint32_t b0, uint32_t b1) {
    asm volatile(
        "mma.sync.aligned.m16n8k16.row.col.f32.bf16.bf16.f32 "
        "{%0,%1,%2,%3}, {%4,%5,%6,%7}, {%8,%9}, {%0,%1,%2,%3};"
        : "+f"(c[0]), "+f"(c[1]), "+f"(c[2]), "+f"(c[3])
        : "r"(a[0]), "r"(a[1]), "r"(a[2]), "r"(a[3]), "r"(b0), "r"(b1));
}

// ---------------- prepass: fp32 -> bf16 hi/lo split ------------------------
__global__ __launch_bounds__(256) void convert_split(const float* __restrict__ X,
                                                     __nv_bfloat16* __restrict__ H,
                                                     __nv_bfloat16* __restrict__ L,
                                                     int n4) {
    int idx = blockIdx.x * 256 + threadIdx.x;
    if (idx >= n4) return;
    float4 v = *(const float4*)(X + (size_t)idx * 4);
    __nv_bfloat16 h0 = __float2bfloat16(v.x), h1 = __float2bfloat16(v.y);
    __nv_bfloat16 h2 = __float2bfloat16(v.z), h3 = __float2bfloat16(v.w);
    __nv_bfloat16 l0 = __float2bfloat16(v.x - __bfloat162float(h0));
    __nv_bfloat16 l1 = __float2bfloat16(v.y - __bfloat162float(h1));
    __nv_bfloat16 l2 = __float2bfloat16(v.z - __bfloat162float(h2));
    __nv_bfloat16 l3 = __float2bfloat16(v.w - __bfloat162float(h3));
    ((__nv_bfloat162*)H)[idx * 2]     = __nv_bfloat162(h0, h1);
    ((__nv_bfloat162*)H)[idx * 2 + 1] = __nv_bfloat162(h2, h3);
    ((__nv_bfloat162*)L)[idx * 2]     = __nv_bfloat162(l0, l1);
    ((__nv_bfloat162*)L)[idx * 2 + 1] = __nv_bfloat162(l2, l3);
}

// W[K][N] fp32 -> Th/Tl[N][K] bf16 (transpose + split)
__global__ __launch_bounds__(256) void transpose_split(const float* __restrict__ W,
                                                       __nv_bfloat16* __restrict__ Th,
                                                       __nv_bfloat16* __restrict__ Tl,
                                                       int K, int N) {
    __shared__ float t[32][33];
    int n = blockIdx.x * 32 + threadIdx.x;
    int k0 = blockIdx.y * 32;
    for (int j = threadIdx.y; j < 32; j += 8)
        t[j][threadIdx.x] = W[(size_t)(k0 + j) * N + n];
    __syncthreads();
    int k = k0 + threadIdx.x;
    for (int j = threadIdx.y; j < 32; j += 8) {
        int nn = blockIdx.x * 32 + j;
        float v = t[threadIdx.x][j];
        __nv_bfloat16 h = __float2bfloat16(v);
        Th[(size_t)nn * K + k] = h;
        Tl[(size_t)nn * K + k] = __float2bfloat16(v - __bfloat162float(h));
    }
}

// ---------------- mma.sync bf16x3 GEMM (unchanged from R8) -----------------
#define BK 32
#define AST 40
#define MAT_BYTES (128 * AST * 2)
#define STAGE_BYTES (4 * MAT_BYTES)
#define GEMM_SMEM (2 * STAGE_BYTES)

__global__ __launch_bounds__(256)
void gemm_bf16x3(const __nv_bfloat16* __restrict__ Ah, const __nv_bfloat16* __restrict__ Al,
                 const __nv_bfloat16* __restrict__ Bh, const __nv_bfloat16* __restrict__ Bl,
                 float* __restrict__ C, int N, int K) {
    extern __shared__ char smc[];
    const uint32_t sb = smem_u32(smc);
    const int tid = threadIdx.x, lane = tid & 31, wid = tid >> 5;
    const int wm = wid & 1, wn = wid >> 1;
    const int m0 = blockIdx.y * 128, n0 = blockIdx.x * 128;
    const __nv_bfloat16* gsrc[4] = { Ah + (size_t)m0 * K, Al + (size_t)m0 * K,
                                     Bh + (size_t)n0 * K, Bl + (size_t)n0 * K };
    const int lrow = tid >> 2, lq = tid & 3;
    const int nch = K / BK;

    float acc[4][4][4];
#pragma unroll
    for (int i = 0; i < 4; i++)
#pragma unroll
        for (int j = 0; j < 4; j++)
#pragma unroll
            for (int q = 0; q < 4; q++) acc[i][j][q] = 0.f;

#pragma unroll
    for (int a = 0; a < 4; a++)
#pragma unroll
        for (int it = 0; it < 2; it++) {
            int r = lrow + it * 64;
            cp_async16(sb + a * MAT_BYTES + (r * AST + lq * 8) * 2,
                       gsrc[a] + (size_t)r * K + lq * 8);
        }
    CP_COMMIT();

    for (int c = 0; c < nch; c++) {
        const int s = c & 1;
        if (c + 1 < nch) {
            uint32_t d0 = sb + (s ^ 1) * STAGE_BYTES;
#pragma unroll
            for (int a = 0; a < 4; a++)
#pragma unroll
                for (int it = 0; it < 2; it++) {
                    int r = lrow + it * 64;
                    cp_async16(d0 + a * MAT_BYTES + (r * AST + lq * 8) * 2,
                               gsrc[a] + (size_t)r * K + (c + 1) * BK + lq * 8);
                }
            CP_COMMIT();
            CP_WAIT(1);
        } else {
            CP_WAIT(0);
        }
        __syncthreads();

        const uint32_t base = sb + s * STAGE_BYTES;
        const int arow = wm * 64 + (lane & 7) + ((lane >> 3) & 1) * 8;
        const int brow = wn * 32 + (lane & 7) + ((lane >> 4) & 1) * 8;
#pragma unroll
        for (int ks = 0; ks < 2; ks++) {
            const int acol = ks * 16 + ((lane >> 4) & 1) * 8;
            const int bcol = ks * 16 + ((lane >> 3) & 1) * 8;
            uint32_t ah[4][4], alr[4][4], bh[2][4], blr[2][4];
#pragma unroll
            for (int mt = 0; mt < 4; mt++) {
                uint32_t ad = base + ((arow + mt * 16) * AST + acol) * 2;
                ldsm4(ah[mt], ad);
                ldsm4(alr[mt], ad + MAT_BYTES);
            }
#pragma unroll
            for (int np = 0; np < 2; np++) {
                uint32_t bd = base + 2 * MAT_BYTES + ((brow + np * 16) * AST + bcol) * 2;
                ldsm4(bh[np], bd);
                ldsm4(blr[np], bd + MAT_BYTES);
            }
#pragma unroll
            for (int mt = 0; mt < 4; mt++)
#pragma unroll
                for (int nt = 0; nt < 4; nt++) {
                    const int np = nt >> 1, off = (nt & 1) * 2;
                    mma16816(acc[mt][nt], ah[mt], bh[np][off], bh[np][off + 1]);
                    mma16816(acc[mt][nt], ah[mt], blr[np][off], blr[np][off + 1]);
                    mma16816(acc[mt][nt], alr[mt], bh[np][off], bh[np][off + 1]);
                }
        }
        __syncthreads();
    }

    const int g = lane >> 2, tg = lane & 3;
#pragma unroll
    for (int mt = 0; mt < 4; mt++)
#pragma unroll
        for (int nt = 0; nt < 4; nt++) {
            int gr = m0 + wm * 64 + mt * 16 + g;
            int gc = n0 + wn * 32 + nt * 8 + tg * 2;
            *(float2*)&C[(size_t)gr * N + gc] = make_float2(acc[mt][nt][0], acc[mt][nt][1]);
            *(float2*)&C[(size_t)(gr + 8) * N + gc] = make_float2(acc[mt][nt][2], acc[mt][nt][3]);
        }
}

// ---------------- RoPE + L2 norm -> bf16 hi/lo splits ----------------------
__global__ __launch_bounds__(64) void rope_norm(const int* __restrict__ pos_ids) {
    const int t = blockIdx.x;
    const int hy = blockIdx.y;  // 0..31 -> Q head, 32..39 -> K head
    const float* X;
    __nv_bfloat16 *H, *L;
    size_t off;
    if (hy < NH) {
        off = (size_t)t * HID_DIM + hy * HD;
        X = g_Q + off; H = g_Qh + off; L = g_Ql + off;
    } else {
        off = (size_t)t * (NKV * HD) + (hy - NH) * HD;
        X = g_K + off; H = g_Kh + off; L = g_Kl + off;
    }

    const int p = threadIdx.x;  // pair 0..63
    float x0 = X[2 * p], x1 = X[2 * p + 1];
    float pos = (float)pos_ids[t];
    float inv = powf(500000.0f, -((float)(2 * p)) / 128.0f);
    float f = pos * inv;
    float c = cosf(f), s = sinf(f);
    float o0 = x0 * c - x1 * s;
    float o1 = x0 * s + x1 * c;

    float ss = o0 * o0 + o1 * o1;
#pragma unroll
    for (int m = 16; m >= 1; m >>= 1) ss += __shfl_xor_sync(0xffffffffu, ss, m);
    __shared__ float sh[2];
    if ((threadIdx.x & 31) == 0) sh[threadIdx.x >> 5] = ss;
    __syncthreads();
    float tot = sh[0] + sh[1];
    float r = rsqrtf(tot / 128.0f + 1e-6f);
    float q0 = o0 * r, q1 = o1 * r;
    __nv_bfloat16 h0 = __float2bfloat16(q0), h1 = __float2bfloat16(q1);
    ((__nv_bfloat162*)H)[p] = __nv_bfloat162(h0, h1);
    ((__nv_bfloat162*)L)[p] = __nv_bfloat162(__float2bfloat16(q0 - __bfloat162float(h0)),
                                             __float2bfloat16(q1 - __bfloat162float(h1)));
}

// ---------------- Attention: tensor-core flash (bf16x3) --------------------
// CTA = 128 q-rows x 1 head. 8 warps, each owns 16 rows. K-tiles of 64.
// smem byte offsets (strides: Q/K/V 136 halves = 272B; P 72 halves = 144B)
#define QH_O 0
#define QL_O 34816
#define KH_O 69632
#define KL_O 87040
#define VH_O 104448
#define VL_O 121856
#define PH_O 139264
#define PL_O 157696
#define ATT_SMEM 176128

__global__ __launch_bounds__(256) void attn_mma(float* __restrict__ wptr) {
    extern __shared__ char smc[];
    const uint32_t sb = smem_u32(smc);
    const int tid = threadIdx.x, lane = tid & 31, wid = tid >> 5;
    const int bx = blockIdx.x;
    const int qt = 15 - (bx >> 5);      // heavy CTAs first
    const int h = bx & 31;
    const int kh = h >> 2;
    const int q0 = qt * 128;
    const float scale = 0.08838834764831845f;

    // load Q tiles (bf16 hi/lo), 128 rows x 128 halves each
    for (int i = tid; i < 4096; i += 256) {
        int mat = i >> 11, r = (i >> 4) & 127, cq = i & 15;
        const __nv_bfloat16* s =
            (mat ? g_Ql : g_Qh) + (size_t)(q0 + r) * HID_DIM + h * HD + cq * 8;
        cp_async16(sb + (mat ? QL_O : QH_O) + r * 272 + cq * 16, s);
    }
    CP_COMMIT();

    float o[16][4];
#pragma unroll
    for (int i = 0; i < 16; i++)
#pragma unroll
        for (int q = 0; q < 4; q++) o[i][q] = 0.f;

    const int g = lane >> 2, tg = lane & 3;
    const int rl0 = wid * 16 + g;           // local row (and +8)
    const int rg0 = q0 + rl0, rg1 = rg0 + 8;
    float m0r = -INFINITY, m1r = -INFINITY, l0r = 0.f, l1r = 0.f;

    const int ktEnd = (q0 + 127) >> 6;
    for (int kt = 0; kt <= ktEnd; kt++) {
        const int k0 = kt * 64;
        // load K,V hi/lo tiles: 4 x (64 rows x 128 halves)
        for (int i = tid; i < 4096; i += 256) {
            int mat = i >> 10, r = (i >> 4) & 63, cq = i & 15;
            const __nv_bfloat16* base =
                (mat == 0) ? g_Kh : (mat == 1) ? g_Kl : (mat == 2) ? g_Vh : g_Vl;
            uint32_t dsto = (mat == 0) ? KH_O : (mat == 1) ? KL_O : (mat == 2) ? VH_O : VL_O;
            cp_async16(sb + dsto + r * 272 + cq * 16,
                       base + (size_t)(k0 + r) * (NKV * HD) + kh * HD + cq * 8);
        }
        CP_COMMIT();
        CP_WAIT(0);
        __syncthreads();

        // ---- S = Q K^T (bf16x3), warp rows wid*16..+15, cols 0..63 ----
        float s[8][4];
#pragma unroll
        for (int nt = 0; nt < 8; nt++)
#pragma unroll
            for (int q = 0; q < 4; q++) s[nt][q] = 0.f;

#pragma unroll
        for (int kc = 0; kc < 8; kc++) {
            uint32_t aaddr = sb + QH_O +
                ((wid * 16 + (lane & 15)) * 136 + kc * 16 + (lane >> 4) * 8) * 2;
            uint32_t ah[4], al[4];
            ldsm4(ah, aaddr);
            ldsm4(al, aaddr + (QL_O - QH_O));
            uint32_t bh[4][4], bl[4][4];
#pragma unroll
            for (int np = 0; np < 4; np++) {
                uint32_t baddr = sb + KH_O +
                    ((np * 16 + (lane & 7) + ((lane >> 4) & 1) * 8) * 136 +
                     kc * 16 + ((lane >> 3) & 1) * 8) * 2;
                ldsm4(bh[np], baddr);
                ldsm4(bl[np], baddr + (KL_O - KH_O));
            }
#pragma unroll
            for (int nt = 0; nt < 8; nt++) {
                const int np = nt >> 1, off = (nt & 1) * 2;
                mma16816(s[nt], ah, bh[np][off], bh[np][off + 1]);
                mma16816(s[nt], ah, bl[np][off], bl[np][off + 1]);
                mma16816(s[nt], al, bh[np][off], bh[np][off + 1]);
            }
        }

        // ---- scale, dump raw, mask, online softmax ----
        float mt0 = -INFINITY, mt1 = -INFINITY;
#pragma unroll
        for (int nt = 0; nt < 8; nt++) {
            s[nt][0] *= scale; s[nt][1] *= scale; s[nt][2] *= scale; s[nt][3] *= scale;
            if (wptr) {
                size_t b0 = ((size_t)h * S_LEN + rg0) * S_LEN + k0 + nt * 8 + tg * 2;
                *(float2*)&wptr[b0] = make_float2(s[nt][0], s[nt][1]);
                *(float2*)&wptr[b0 + (size_t)8 * S_LEN] = make_float2(s[nt][2], s[nt][3]);
            }
            const int c0 = k0 + nt * 8 + tg * 2;
            if (c0 > rg0) s[nt][0] = -INFINITY;
            if (c0 + 1 > rg0) s[nt][1] = -INFINITY;
            if (c0 > rg1) s[nt][2] = -INFINITY;
            if (c0 + 1 > rg1) s[nt][3] = -INFINITY;
            mt0 = fmaxf(mt0, fmaxf(s[nt][0], s[nt][1]));
            mt1 = fmaxf(mt1, fmaxf(s[nt][2], s[nt][3]));
        }
        mt0 = fmaxf(mt0, __shfl_xor_sync(0xffffffffu, mt0, 1));
        mt0 = fmaxf(mt0, __shfl_xor_sync(0xffffffffu, mt0, 2));
        mt1 = fmaxf(mt1, __shfl_xor_sync(0xffffffffu, mt1, 1));
        mt1 = fmaxf(mt1, __shfl_xor_sync(0xffffffffu, mt1, 2));

        const float mn0 = fmaxf(m0r, mt0), mn1 = fmaxf(m1r, mt1);
        const float f0 = expf(m0r - mn0), f1 = expf(m1r - mn1);
        m0r = mn0; m1r = mn1;

        float rs0 = 0.f, rs1 = 0.f;
#pragma unroll
        for (int nt = 0; nt < 8; nt++) {
            float p0 = expf(s[nt][0] - mn0), p1 = expf(s[nt][1] - mn0);
            float p2 = expf(s[nt][2] - mn1), p3 = expf(s[nt][3] - mn1);
            rs0 += p0 + p1;
            rs1 += p2 + p3;
            __nv_bfloat16 h0 = __float2bfloat16(p0), h1 = __float2bfloat16(p1);
            __nv_bfloat16 h2 = __float2bfloat16(p2), h3 = __float2bfloat16(p3);
            uint32_t po = (rl0 * 72 + nt * 8 + tg * 2) * 2;
            *(__nv_bfloat162*)(smc + PH_O + po) = __nv_bfloat162(h0, h1);
            *(__nv_bfloat162*)(smc + PH_O + po + 8 * 144) = __nv_bfloat162(h2, h3);
            *(__nv_bfloat162*)(smc + PL_O + po) =
                __nv_bfloat162(__float2bfloat16(p0 - __bfloat162float(h0)),
                               __float2bfloat16(p1 - __bfloat162float(h1)));
            *(__nv_bfloat162*)(smc + PL_O + po + 8 * 144) =
                __nv_bfloat162(__float2bfloat16(p2 - __bfloat162float(h2)),
                               __float2bfloat16(p3 - __bfloat162float(h3)));
        }
        rs0 += __shfl_xor_sync(0xffffffffu, rs0, 1);
        rs0 += __shfl_xor_sync(0xffffffffu, rs0, 2);
        rs1 += __shfl_xor_sync(0xffffffffu, rs1, 1);
        rs1 += __shfl_xor_sync(0xffffffffu, rs1, 2);
        l0r = l0r * f0 + rs0;
        l1r = l1r * f1 + rs1;
#pragma unroll
        for (int nt = 0; nt < 16; nt++) {
            o[nt][0] *= f0; o[nt][1] *= f0; o[nt][2] *= f1; o[nt][3] *= f1;
        }
        __syncwarp();

        // ---- O += P V (bf16x3); V via ldmatrix.trans ----
#pragma unroll
        for (int kc = 0; kc < 4; kc++) {
            uint32_t paddr = sb + PH_O +
                ((wid * 16 + (lane & 15)) * 72 + kc * 16 + (lane >> 4) * 8) * 2;
            uint32_t ap[4], apl[4];
            ldsm4(ap, paddr);
            ldsm4(apl, paddr + (PL_O - PH_O));
#pragma unroll
            for (int ng = 0; ng < 8; ng++) {
                uint32_t vaddr = sb + VH_O +
                    ((kc * 16 + (lane & 15)) * 136 + ng * 16 + (lane >> 4) * 8) * 2;
                uint32_t dh[4], dl[4];
                ldsm4t(dh, vaddr);
                ldsm4t(dl, vaddr + (VL_O - VH_O));
                mma16816(o[2 * ng],     ap,  dh[0], dh[1]);
                mma16816(o[2 * ng + 1], ap,  dh[2], dh[3]);
                mma16816(o[2 * ng],     ap,  dl[0], dl[1]);
                mma16816(o[2 * ng + 1], ap,  dl[2], dl[3]);
                mma16816(o[2 * ng],     apl, dh[0], dh[1]);
                mma16816(o[2 * ng + 1], apl, dh[2], dh[3]);
            }
        }
        __syncthreads();
    }

    // epilogue
    const float inv0 = 1.0f / l0r, inv1 = 1.0f / l1r;
#pragma unroll
    for (int nt = 0; nt < 16; nt++) {
        int col = nt * 8 + tg * 2;
        size_t b0 = (size_t)rg0 * HID_DIM + h * HD + col;
        *(float2*)&g_attn[b0] = make_float2(o[nt][0] * inv0, o[nt][1] * inv0);
        *(float2*)&g_attn[b0 + (size_t)8 * HID_DIM] =
            make_float2(o[nt][2] * inv1, o[nt][3] * inv1);
    }
    if (tg == 0) {
        g_m[h * S_LEN + rg0] = m0r;
        g_l[h * S_LEN + rg0] = l0r;
        g_m[h * S_LEN + rg1] = m1r;
        g_l[h * S_LEN + rg1] = l1r;
    }
}

// ---------------- pass 2: normalize dumped scores -> weights ---------------
__global__ __launch_bounds__(256) void softmax_norm(float* __restrict__ w) {
    size_t t = (size_t)blockIdx.x * 256 + threadIdx.x;
    size_t e = t * 4;
    int h = (int)(e >> 22);
    int i = (int)((e >> 11) & 2047);
    int j = (int)(e & 2047);
    float4* p = (float4*)(w + e);
    if (j > i) {
        *p = make_float4(0.f, 0.f, 0.f, 0.f);
        return;
    }
    float m = g_m[h * S_LEN + i];
    float inv = 1.0f / g_l[h * S_LEN + i];
    float4 s4 = *p;
    float4 o;
    o.x = expf(s4.x - m) * inv;
    o.y = (j + 1 <= i) ? expf(s4.y - m) * inv : 0.f;
    o.z = (j + 2 <= i) ? expf(s4.z - m) * inv : 0.f;
    o.w = (j + 3 <= i) ? expf(s4.w - m) * inv : 0.f;
    *p = o;
}

// ---------------- launcher --------------------------------------------------
extern "C" void kernel_launch(void* const* d_in, const int* in_sizes, int n_in,
                              void* d_out, int out_size) {
    const float* hidden = (const float*)d_in[0];
    const int* pos = (const int*)d_in[2];
    const float* Wq = (const float*)d_in[3];
    const float* Wk = (const float*)d_in[4];
    const float* Wv = (const float*)d_in[5];
    const float* Wo = (const float*)d_in[6];

    float *qp, *kp, *vp, *ap;
    cudaGetSymbolAddress((void**)&qp, g_Q);
    cudaGetSymbolAddress((void**)&kp, g_K);
    cudaGetSymbolAddress((void**)&vp, g_V);
    cudaGetSymbolAddress((void**)&ap, g_attn);
    __nv_bfloat16 *ah, *al, *wqh, *wql, *wkh, *wkl, *wvh, *wvl, *woh, *wol, *vh, *vl;
    cudaGetSymbolAddress((void**)&ah, g_Ah);
    cudaGetSymbolAddress((void**)&al, g_Al);
    cudaGetSymbolAddress((void**)&wqh, g_WqTh);
    cudaGetSymbolAddress((void**)&wql, g_WqTl);
    cudaGetSymbolAddress((void**)&wkh, g_WkTh);
    cudaGetSymbolAddress((void**)&wkl, g_WkTl);
    cudaGetSymbolAddress((void**)&wvh, g_WvTh);
    cudaGetSymbolAddress((void**)&wvl, g_WvTl);
    cudaGetSymbolAddress((void**)&woh, g_WoTh);
    cudaGetSymbolAddress((void**)&wol, g_WoTl);
    cudaGetSymbolAddress((void**)&vh, g_Vh);
    cudaGetSymbolAddress((void**)&vl, g_Vl);

    float* out = (float*)d_out;
    const long long ATTN_N = (long long)S_LEN * HID_DIM;
    const long long WEI_N = (long long)NH * S_LEN * S_LEN;
    float* obase = nullptr;
    float* wbase = nullptr;
    long long osz = (long long)out_size;
    if (osz >= ATTN_N + WEI_N) { obase = out; wbase = out + ATTN_N; }
    else if (osz == WEI_N)     { wbase = out; }
    else                       { obase = out; }

    cudaFuncSetAttribute(gemm_bf16x3, cudaFuncAttributeMaxDynamicSharedMemorySize, GEMM_SMEM);
    cudaFuncSetAttribute(attn_mma, cudaFuncAttributeMaxDynamicSharedMemorySize, ATT_SMEM);

    // prepass: split hidden, transpose+split weights
    convert_split<<<(S_LEN * HID_DIM) / 1024, 256>>>(hidden, ah, al, (S_LEN * HID_DIM) / 4);
    transpose_split<<<dim3(HID_DIM / 32, HID_DIM / 32), dim3(32, 8)>>>(Wq, wqh, wql, HID_DIM, HID_DIM);
    transpose_split<<<dim3((NKV * HD) / 32, HID_DIM / 32), dim3(32, 8)>>>(Wk, wkh, wkl, HID_DIM, NKV * HD);
    transpose_split<<<dim3((NKV * HD) / 32, HID_DIM / 32), dim3(32, 8)>>>(Wv, wvh, wvl, HID_DIM, NKV * HD);
    transpose_split<<<dim3(HID_DIM / 32, HID_DIM / 32), dim3(32, 8)>>>(Wo, woh, wol, HID_DIM, HID_DIM);

    // projections (tensor cores)
    gemm_bf16x3<<<dim3(32, 16), 256, GEMM_SMEM>>>(ah, al, wqh, wql, qp, HID_DIM, HID_DIM);
    gemm_bf16x3<<<dim3(8, 16),  256, GEMM_SMEM>>>(ah, al, wkh, wkl, kp, NKV * HD, HID_DIM);
    gemm_bf16x3<<<dim3(8, 16),  256, GEMM_SMEM>>>(ah, al, wvh, wvl, vp, NKV * HD, HID_DIM);

    // rope + l2norm -> bf16 splits; V split
    rope_norm<<<dim3(S_LEN, NH + NKV), 64>>>(pos);
    convert_split<<<(S_LEN * NKV * HD) / 1024, 256>>>(vp, vh, vl, (S_LEN * NKV * HD) / 4);

    // tensor-core flash attention (+ raw score dump)
    attn_mma<<<512, 256, ATT_SMEM>>>(wbase);

    if (wbase) softmax_norm<<<(unsigned)(WEI_N / 4 / 256), 256>>>(wbase);

    if (obase) {
        convert_split<<<(S_LEN * HID_DIM) / 1024, 256>>>(ap, ah, al, (S_LEN * HID_DIM) / 4);
        gemm_bf16x3<<<dim3(32, 16), 256, GEMM_SMEM>>>(ah, al, woh, wol, obase, HID_DIM, HID_DIM);
    }
}

// round 13
// speedup vs baseline: 2.7723x; 1.0174x over previous
#include <cuda_runtime.h>
#include <cuda_bf16.h>
#include <math.h>
#include <stdint.h>

#define S_LEN 2048
#define HID_DIM 4096
#define NH 32
#define NKV 8
#define HD 128

// ---------------- scratch (device globals; no allocation allowed) ----------
__device__ float g_Q[(size_t)S_LEN * NH * HD];
__device__ float g_K[(size_t)S_LEN * NKV * HD];
__device__ float g_V[(size_t)S_LEN * NKV * HD];
__device__ float g_attn[(size_t)S_LEN * NH * HD];
__device__ float g_m[NH * S_LEN];
__device__ float g_l[NH * S_LEN];

__device__ __nv_bfloat16 g_Ah[(size_t)S_LEN * HID_DIM];
__device__ __nv_bfloat16 g_Al[(size_t)S_LEN * HID_DIM];
__device__ __nv_bfloat16 g_WqTh[(size_t)HID_DIM * HID_DIM];   // [N][K]
__device__ __nv_bfloat16 g_WqTl[(size_t)HID_DIM * HID_DIM];
__device__ __nv_bfloat16 g_WkTh[(size_t)(NKV * HD) * HID_DIM];
__device__ __nv_bfloat16 g_WkTl[(size_t)(NKV * HD) * HID_DIM];
__device__ __nv_bfloat16 g_WvTh[(size_t)(NKV * HD) * HID_DIM];
__device__ __nv_bfloat16 g_WvTl[(size_t)(NKV * HD) * HID_DIM];
__device__ __nv_bfloat16 g_WoTh[(size_t)HID_DIM * HID_DIM];
__device__ __nv_bfloat16 g_WoTl[(size_t)HID_DIM * HID_DIM];
__device__ __nv_bfloat16 g_Qh[(size_t)S_LEN * NH * HD];
__device__ __nv_bfloat16 g_Ql[(size_t)S_LEN * NH * HD];
__device__ __nv_bfloat16 g_Kh[(size_t)S_LEN * NKV * HD];
__device__ __nv_bfloat16 g_Kl[(size_t)S_LEN * NKV * HD];
__device__ __nv_bfloat16 g_Vh[(size_t)S_LEN * NKV * HD];
__device__ __nv_bfloat16 g_Vl[(size_t)S_LEN * NKV * HD];

// ---------------- PTX helpers ----------------------------------------------
__device__ __forceinline__ uint32_t smem_u32(const void* p) {
    uint32_t a;
    asm("{ .reg .u64 t; cvta.to.shared.u64 t, %1; cvt.u32.u64 %0, t; }"
        : "=r"(a) : "l"(p));
    return a;
}
__device__ __forceinline__ void cp_async16(uint32_t dst, const void* src) {
    asm volatile("cp.async.cg.shared.global [%0], [%1], 16;" :: "r"(dst), "l"(src));
}
#define CP_COMMIT() asm volatile("cp.async.commit_group;" ::: "memory")
#define CP_WAIT(n)  asm volatile("cp.async.wait_group %0;" :: "n"(n) : "memory")

__device__ __forceinline__ void ldsm4(uint32_t (&r)[4], uint32_t addr) {
    asm volatile("ldmatrix.sync.aligned.m8n8.x4.shared.b16 {%0,%1,%2,%3}, [%4];"
                 : "=r"(r[0]), "=r"(r[1]), "=r"(r[2]), "=r"(r[3]) : "r"(addr));
}
__device__ __forceinline__ void ldsm4t(uint32_t (&r)[4], uint32_t addr) {
    asm volatile("ldmatrix.sync.aligned.m8n8.x4.trans.shared.b16 {%0,%1,%2,%3}, [%4];"
                 : "=r"(r[0]), "=r"(r[1]), "=r"(r[2]), "=r"(r[3]) : "r"(addr));
}
__device__ __forceinline__ void mma16816(float (&c)[4], const uint32_t (&a)[4],
                                         uint32_t b0, uint32_t b1) {
    asm volatile(
        "mma.sync.aligned.m16n8k16.row.col.f32.bf16.bf16.f32 "
        "{%0,%1,%2,%3}, {%4,%5,%6,%7}, {%8,%9}, {%0,%1,%2,%3};"
        : "+f"(c[0]), "+f"(c[1]), "+f"(c[2]), "+f"(c[3])
        : "r"(a[0]), "r"(a[1]), "r"(a[2]), "r"(a[3]), "r"(b0), "r"(b1));
}

// ---------------- prepass kernels ------------------------------------------
__global__ __launch_bounds__(256) void convert_split(const float* __restrict__ X,
                                                     __nv_bfloat16* __restrict__ H,
                                                     __nv_bfloat16* __restrict__ L,
                                                     int n4) {
    int idx = blockIdx.x * 256 + threadIdx.x;
    if (idx >= n4) return;
    float4 v = *(const float4*)(X + (size_t)idx * 4);
    __nv_bfloat16 h0 = __float2bfloat16(v.x), h1 = __float2bfloat16(v.y);
    __nv_bfloat16 h2 = __float2bfloat16(v.z), h3 = __float2bfloat16(v.w);
    __nv_bfloat16 l0 = __float2bfloat16(v.x - __bfloat162float(h0));
    __nv_bfloat16 l1 = __float2bfloat16(v.y - __bfloat162float(h1));
    __nv_bfloat16 l2 = __float2bfloat16(v.z - __bfloat162float(h2));
    __nv_bfloat16 l3 = __float2bfloat16(v.w - __bfloat162float(h3));
    ((__nv_bfloat162*)H)[idx * 2]     = __nv_bfloat162(h0, h1);
    ((__nv_bfloat162*)H)[idx * 2 + 1] = __nv_bfloat162(h2, h3);
    ((__nv_bfloat162*)L)[idx * 2]     = __nv_bfloat162(l0, l1);
    ((__nv_bfloat162*)L)[idx * 2 + 1] = __nv_bfloat162(l2, l3);
}

__global__ __launch_bounds__(256) void transpose_split(const float* __restrict__ W,
                                                       __nv_bfloat16* __restrict__ Th,
                                                       __nv_bfloat16* __restrict__ Tl,
                                                       int K, int N) {
    __shared__ float t[32][33];
    int n = blockIdx.x * 32 + threadIdx.x;
    int k0 = blockIdx.y * 32;
    for (int j = threadIdx.y; j < 32; j += 8)
        t[j][threadIdx.x] = W[(size_t)(k0 + j) * N + n];
    __syncthreads();
    int k = k0 + threadIdx.x;
    for (int j = threadIdx.y; j < 32; j += 8) {
        int nn = blockIdx.x * 32 + j;
        float v = t[threadIdx.x][j];
        __nv_bfloat16 h = __float2bfloat16(v);
        Th[(size_t)nn * K + k] = h;
        Tl[(size_t)nn * K + k] = __float2bfloat16(v - __bfloat162float(h));
    }
}

// ---------------- bf16x3 GEMM core: 3-stage cp.async pipeline --------------
#define BK 32
#define AST 40
#define MAT_BYTES (128 * AST * 2)
#define STAGE_BYTES (4 * MAT_BYTES)
#define GEMM_SMEM (3 * STAGE_BYTES)

__device__ __forceinline__ void gemm_core(const __nv_bfloat16* __restrict__ Ah,
                                          const __nv_bfloat16* __restrict__ Al,
                                          const __nv_bfloat16* __restrict__ Bh,
                                          const __nv_bfloat16* __restrict__ Bl,
                                          float* __restrict__ C, int N, int K,
                                          int m0, int n0, char* smc) {
    const uint32_t sb = smem_u32(smc);
    const int tid = threadIdx.x, lane = tid & 31, wid = tid >> 5;
    const int wm = wid & 1, wn = wid >> 1;
    const __nv_bfloat16* gsrc[4] = { Ah + (size_t)m0 * K, Al + (size_t)m0 * K,
                                     Bh + (size_t)n0 * K, Bl + (size_t)n0 * K };
    const int lrow = tid >> 2, lq = tid & 3;
    const int nch = K / BK;

    float acc[4][4][4];
#pragma unroll
    for (int i = 0; i < 4; i++)
#pragma unroll
        for (int j = 0; j < 4; j++)
#pragma unroll
            for (int q = 0; q < 4; q++) acc[i][j][q] = 0.f;

    // prologue: stage 0 <- chunk 0, stage 1 <- chunk 1
#pragma unroll
    for (int pc = 0; pc < 2; pc++) {
        uint32_t d0 = sb + pc * STAGE_BYTES;
#pragma unroll
        for (int a = 0; a < 4; a++)
#pragma unroll
            for (int it = 0; it < 2; it++) {
                int r = lrow + it * 64;
                cp_async16(d0 + a * MAT_BYTES + (r * AST + lq * 8) * 2,
                           gsrc[a] + (size_t)r * K + pc * BK + lq * 8);
            }
        CP_COMMIT();
    }

    int st = 0, stw = 2;
    for (int c = 0; c < nch; c++) {
        if (c == nch - 1) { CP_WAIT(0); } else { CP_WAIT(1); }
        __syncthreads();
        if (c + 2 < nch) {
            uint32_t d0 = sb + stw * STAGE_BYTES;
#pragma unroll
            for (int a = 0; a < 4; a++)
#pragma unroll
                for (int it = 0; it < 2; it++) {
                    int r = lrow + it * 64;
                    cp_async16(d0 + a * MAT_BYTES + (r * AST + lq * 8) * 2,
                               gsrc[a] + (size_t)r * K + (c + 2) * BK + lq * 8);
                }
            CP_COMMIT();
        }

        const uint32_t base = sb + st * STAGE_BYTES;
        const int arow = wm * 64 + (lane & 7) + ((lane >> 3) & 1) * 8;
        const int brow = wn * 32 + (lane & 7) + ((lane >> 4) & 1) * 8;
#pragma unroll
        for (int ks = 0; ks < 2; ks++) {
            const int acol = ks * 16 + ((lane >> 4) & 1) * 8;
            const int bcol = ks * 16 + ((lane >> 3) & 1) * 8;
            uint32_t ah[4][4], alr[4][4], bh[2][4], blr[2][4];
#pragma unroll
            for (int mt = 0; mt < 4; mt++) {
                uint32_t ad = base + ((arow + mt * 16) * AST + acol) * 2;
                ldsm4(ah[mt], ad);
                ldsm4(alr[mt], ad + MAT_BYTES);
            }
#pragma unroll
            for (int np = 0; np < 2; np++) {
                uint32_t bd = base + 2 * MAT_BYTES + ((brow + np * 16) * AST + bcol) * 2;
                ldsm4(bh[np], bd);
                ldsm4(blr[np], bd + MAT_BYTES);
            }
#pragma unroll
            for (int mt = 0; mt < 4; mt++)
#pragma unroll
                for (int nt = 0; nt < 4; nt++) {
                    const int np = nt >> 1, off = (nt & 1) * 2;
                    mma16816(acc[mt][nt], ah[mt], bh[np][off], bh[np][off + 1]);
                    mma16816(acc[mt][nt], ah[mt], blr[np][off], blr[np][off + 1]);
                    mma16816(acc[mt][nt], alr[mt], bh[np][off], bh[np][off + 1]);
                }
        }
        st = (st == 2) ? 0 : st + 1;
        stw = (stw == 2) ? 0 : stw + 1;
    }

    const int g = lane >> 2, tg = lane & 3;
#pragma unroll
    for (int mt = 0; mt < 4; mt++)
#pragma unroll
        for (int nt = 0; nt < 4; nt++) {
            int gr = m0 + wm * 64 + mt * 16 + g;
            int gc = n0 + wn * 32 + nt * 8 + tg * 2;
            *(float2*)&C[(size_t)gr * N + gc] = make_float2(acc[mt][nt][0], acc[mt][nt][1]);
            *(float2*)&C[(size_t)(gr + 8) * N + gc] = make_float2(acc[mt][nt][2], acc[mt][nt][3]);
        }
}

// fused QKV projection: grid (48, 16); n-tiles 0..31 Q, 32..39 K, 40..47 V
__global__ __launch_bounds__(256) void gemm_qkv() {
    extern __shared__ char smc[];
    const int nt = blockIdx.x, m0 = blockIdx.y * 128;
    const __nv_bfloat16 *bh_, *bl_;
    float* c_;
    int nOut, n0;
    if (nt < 32)      { bh_ = g_WqTh; bl_ = g_WqTl; c_ = g_Q; nOut = HID_DIM;  n0 = nt * 128; }
    else if (nt < 40) { bh_ = g_WkTh; bl_ = g_WkTl; c_ = g_K; nOut = NKV * HD; n0 = (nt - 32) * 128; }
    else              { bh_ = g_WvTh; bl_ = g_WvTl; c_ = g_V; nOut = NKV * HD; n0 = (nt - 40) * 128; }
    gemm_core(g_Ah, g_Al, bh_, bl_, c_, nOut, HID_DIM, m0, n0, smc);
}

__global__ __launch_bounds__(256) void gemm_plain(const __nv_bfloat16* __restrict__ Ah,
                                                  const __nv_bfloat16* __restrict__ Al,
                                                  const __nv_bfloat16* __restrict__ Bh,
                                                  const __nv_bfloat16* __restrict__ Bl,
                                                  float* __restrict__ C, int N, int K) {
    extern __shared__ char smc[];
    gemm_core(Ah, Al, Bh, Bl, C, N, K, blockIdx.y * 128, blockIdx.x * 128, smc);
}

// ---------------- RoPE + L2 norm -> bf16 hi/lo splits ----------------------
__global__ __launch_bounds__(64) void rope_norm(const int* __restrict__ pos_ids) {
    const int t = blockIdx.x;
    const int hy = blockIdx.y;
    const float* X;
    __nv_bfloat16 *H, *L;
    size_t off;
    if (hy < NH) {
        off = (size_t)t * HID_DIM + hy * HD;
        X = g_Q + off; H = g_Qh + off; L = g_Ql + off;
    } else {
        off = (size_t)t * (NKV * HD) + (hy - NH) * HD;
        X = g_K + off; H = g_Kh + off; L = g_Kl + off;
    }

    const int p = threadIdx.x;
    float x0 = X[2 * p], x1 = X[2 * p + 1];
    float pos = (float)pos_ids[t];
    float inv = powf(500000.0f, -((float)(2 * p)) / 128.0f);
    float f = pos * inv;
    float c = cosf(f), s = sinf(f);
    float o0 = x0 * c - x1 * s;
    float o1 = x0 * s + x1 * c;

    float ss = o0 * o0 + o1 * o1;
#pragma unroll
    for (int m = 16; m >= 1; m >>= 1) ss += __shfl_xor_sync(0xffffffffu, ss, m);
    __shared__ float sh[2];
    if ((threadIdx.x & 31) == 0) sh[threadIdx.x >> 5] = ss;
    __syncthreads();
    float tot = sh[0] + sh[1];
    float r = rsqrtf(tot / 128.0f + 1e-6f);
    float q0 = o0 * r, q1 = o1 * r;
    __nv_bfloat16 h0 = __float2bfloat16(q0), h1 = __float2bfloat16(q1);
    ((__nv_bfloat162*)H)[p] = __nv_bfloat162(h0, h1);
    ((__nv_bfloat162*)L)[p] = __nv_bfloat162(__float2bfloat16(q0 - __bfloat162float(h0)),
                                             __float2bfloat16(q1 - __bfloat162float(h1)));
}

// ---------------- Attention: tensor-core flash (bf16x3), K/V overlap -------
#define QH_O 0
#define QL_O 34816
#define KH_O 69632
#define KL_O 87040
#define VH_O 104448
#define VL_O 121856
#define PH_O 139264
#define PL_O 157696
#define ATT_SMEM 176128

__global__ __launch_bounds__(256) void attn_mma(float* __restrict__ wptr) {
    extern __shared__ char smc[];
    const uint32_t sb = smem_u32(smc);
    const int tid = threadIdx.x, lane = tid & 31, wid = tid >> 5;
    const int bx = blockIdx.x;
    const int qt = 15 - (bx >> 5);
    const int h = bx & 31;
    const int kh = h >> 2;
    const int q0 = qt * 128;
    const float scale = 0.08838834764831845f;

    // Q tiles (group 1)
    for (int i = tid; i < 4096; i += 256) {
        int mat = i >> 11, r = (i >> 4) & 127, cq = i & 15;
        const __nv_bfloat16* s =
            (mat ? g_Ql : g_Qh) + (size_t)(q0 + r) * HID_DIM + h * HD + cq * 8;
        cp_async16(sb + (mat ? QL_O : QH_O) + r * 272 + cq * 16, s);
    }
    CP_COMMIT();

    // K (group), V (group)
    auto issueK = [&](int k0) {
        for (int i = tid; i < 2048; i += 256) {
            int mat = i >> 10, r = (i >> 4) & 63, cq = i & 15;
            cp_async16(sb + (mat ? KL_O : KH_O) + r * 272 + cq * 16,
                       (mat ? g_Kl : g_Kh) + (size_t)(k0 + r) * (NKV * HD) + kh * HD + cq * 8);
        }
        CP_COMMIT();
    };
    auto issueV = [&](int k0) {
        for (int i = tid; i < 2048; i += 256) {
            int mat = i >> 10, r = (i >> 4) & 63, cq = i & 15;
            cp_async16(sb + (mat ? VL_O : VH_O) + r * 272 + cq * 16,
                       (mat ? g_Vl : g_Vh) + (size_t)(k0 + r) * (NKV * HD) + kh * HD + cq * 8);
        }
        CP_COMMIT();
    };
    issueK(0);
    issueV(0);

    float o[16][4];
#pragma unroll
    for (int i = 0; i < 16; i++)
#pragma unroll
        for (int q = 0; q < 4; q++) o[i][q] = 0.f;

    const int g = lane >> 2, tg = lane & 3;
    const int rl0 = wid * 16 + g;
    const int rg0 = q0 + rl0, rg1 = rg0 + 8;
    float m0r = -INFINITY, m1r = -INFINITY, l0r = 0.f, l1r = 0.f;

    const int ktEnd = (q0 + 127) >> 6;
    for (int kt = 0; kt <= ktEnd; kt++) {
        const int k0 = kt * 64;
        CP_WAIT(1);          // Q (first iter) + K_kt complete; V_kt may be in flight
        __syncthreads();

        // ---- S = Q K^T ----
        float s[8][4];
#pragma unroll
        for (int nt = 0; nt < 8; nt++)
#pragma unroll
            for (int q = 0; q < 4; q++) s[nt][q] = 0.f;

#pragma unroll
        for (int kc = 0; kc < 8; kc++) {
            uint32_t aaddr = sb + QH_O +
                ((wid * 16 + (lane & 15)) * 136 + kc * 16 + (lane >> 4) * 8) * 2;
            uint32_t ah[4], al[4];
            ldsm4(ah, aaddr);
            ldsm4(al, aaddr + (QL_O - QH_O));
            uint32_t bh[4][4], bl[4][4];
#pragma unroll
            for (int np = 0; np < 4; np++) {
                uint32_t baddr = sb + KH_O +
                    ((np * 16 + (lane & 7) + ((lane >> 4) & 1) * 8) * 136 +
                     kc * 16 + ((lane >> 3) & 1) * 8) * 2;
                ldsm4(bh[np], baddr);
                ldsm4(bl[np], baddr + (KL_O - KH_O));
            }
#pragma unroll
            for (int nt = 0; nt < 8; nt++) {
                const int np = nt >> 1, off = (nt & 1) * 2;
                mma16816(s[nt], ah, bh[np][off], bh[np][off + 1]);
                mma16816(s[nt], ah, bl[np][off], bl[np][off + 1]);
                mma16816(s[nt], al, bh[np][off], bh[np][off + 1]);
            }
        }
        __syncthreads();                  // all warps done reading K tile
        if (kt < ktEnd) issueK(k0 + 64);  // prefetch next K over softmax+PV

        // ---- scale, dump raw, mask, online softmax ----
        float mt0 = -INFINITY, mt1 = -INFINITY;
#pragma unroll
        for (int nt = 0; nt < 8; nt++) {
            s[nt][0] *= scale; s[nt][1] *= scale; s[nt][2] *= scale; s[nt][3] *= scale;
            if (wptr) {
                size_t b0 = ((size_t)h * S_LEN + rg0) * S_LEN + k0 + nt * 8 + tg * 2;
                *(float2*)&wptr[b0] = make_float2(s[nt][0], s[nt][1]);
                *(float2*)&wptr[b0 + (size_t)8 * S_LEN] = make_float2(s[nt][2], s[nt][3]);
            }
            const int c0 = k0 + nt * 8 + tg * 2;
            if (c0 > rg0) s[nt][0] = -INFINITY;
            if (c0 + 1 > rg0) s[nt][1] = -INFINITY;
            if (c0 > rg1) s[nt][2] = -INFINITY;
            if (c0 + 1 > rg1) s[nt][3] = -INFINITY;
            mt0 = fmaxf(mt0, fmaxf(s[nt][0], s[nt][1]));
            mt1 = fmaxf(mt1, fmaxf(s[nt][2], s[nt][3]));
        }
        mt0 = fmaxf(mt0, __shfl_xor_sync(0xffffffffu, mt0, 1));
        mt0 = fmaxf(mt0, __shfl_xor_sync(0xffffffffu, mt0, 2));
        mt1 = fmaxf(mt1, __shfl_xor_sync(0xffffffffu, mt1, 1));
        mt1 = fmaxf(mt1, __shfl_xor_sync(0xffffffffu, mt1, 2));

        const float mn0 = fmaxf(m0r, mt0), mn1 = fmaxf(m1r, mt1);
        const float f0 = __expf(m0r - mn0), f1 = __expf(m1r - mn1);
        m0r = mn0; m1r = mn1;

        float rs0 = 0.f, rs1 = 0.f;
#pragma unroll
        for (int nt = 0; nt < 8; nt++) {
            float p0 = __expf(s[nt][0] - mn0), p1 = __expf(s[nt][1] - mn0);
            float p2 = __expf(s[nt][2] - mn1), p3 = __expf(s[nt][3] - mn1);
            rs0 += p0 + p1;
            rs1 += p2 + p3;
            __nv_bfloat16 h0 = __float2bfloat16(p0), h1 = __float2bfloat16(p1);
            __nv_bfloat16 h2 = __float2bfloat16(p2), h3 = __float2bfloat16(p3);
            uint32_t po = (rl0 * 72 + nt * 8 + tg * 2) * 2;
            *(__nv_bfloat162*)(smc + PH_O + po) = __nv_bfloat162(h0, h1);
            *(__nv_bfloat162*)(smc + PH_O + po + 8 * 144) = __nv_bfloat162(h2, h3);
            *(__nv_bfloat162*)(smc + PL_O + po) =
                __nv_bfloat162(__float2bfloat16(p0 - __bfloat162float(h0)),
                               __float2bfloat16(p1 - __bfloat162float(h1)));
            *(__nv_bfloat162*)(smc + PL_O + po + 8 * 144) =
                __nv_bfloat162(__float2bfloat16(p2 - __bfloat162float(h2)),
                               __float2bfloat16(p3 - __bfloat162float(h3)));
        }
        rs0 += __shfl_xor_sync(0xffffffffu, rs0, 1);
        rs0 += __shfl_xor_sync(0xffffffffu, rs0, 2);
        rs1 += __shfl_xor_sync(0xffffffffu, rs1, 1);
        rs1 += __shfl_xor_sync(0xffffffffu, rs1, 2);
        l0r = l0r * f0 + rs0;
        l1r = l1r * f1 + rs1;
#pragma unroll
        for (int nt = 0; nt < 16; nt++) {
            o[nt][0] *= f0; o[nt][1] *= f0; o[nt][2] *= f1; o[nt][3] *= f1;
        }

        if (kt == ktEnd) { CP_WAIT(0); } else { CP_WAIT(1); }  // V_kt ready
        __syncwarp();

        // ---- O += P V ----
#pragma unroll
        for (int kc = 0; kc < 4; kc++) {
            uint32_t paddr = sb + PH_O +
                ((wid * 16 + (lane & 15)) * 72 + kc * 16 + (lane >> 4) * 8) * 2;
            uint32_t ap[4], apl[4];
            ldsm4(ap, paddr);
            ldsm4(apl, paddr + (PL_O - PH_O));
#pragma unroll
            for (int ng = 0; ng < 8; ng++) {
                uint32_t vaddr = sb + VH_O +
                    ((kc * 16 + (lane & 15)) * 136 + ng * 16 + (lane >> 4) * 8) * 2;
                uint32_t dh[4], dl[4];
                ldsm4t(dh, vaddr);
                ldsm4t(dl, vaddr + (VL_O - VH_O));
                mma16816(o[2 * ng],     ap,  dh[0], dh[1]);
                mma16816(o[2 * ng + 1], ap,  dh[2], dh[3]);
                mma16816(o[2 * ng],     ap,  dl[0], dl[1]);
                mma16816(o[2 * ng + 1], ap,  dl[2], dl[3]);
                mma16816(o[2 * ng],     apl, dh[0], dh[1]);
                mma16816(o[2 * ng + 1], apl, dh[2], dh[3]);
            }
        }
        __syncthreads();                  // all warps done reading V tile
        if (kt < ktEnd) issueV(k0 + 64);  // prefetch next V over next S
    }

    const float inv0 = 1.0f / l0r, inv1 = 1.0f / l1r;
#pragma unroll
    for (int nt = 0; nt < 16; nt++) {
        int col = nt * 8 + tg * 2;
        size_t b0 = (size_t)rg0 * HID_DIM + h * HD + col;
        *(float2*)&g_attn[b0] = make_float2(o[nt][0] * inv0, o[nt][1] * inv0);
        *(float2*)&g_attn[b0 + (size_t)8 * HID_DIM] =
            make_float2(o[nt][2] * inv1, o[nt][3] * inv1);
    }
    if (tg == 0) {
        g_m[h * S_LEN + rg0] = m0r;
        g_l[h * S_LEN + rg0] = l0r;
        g_m[h * S_LEN + rg1] = m1r;
        g_l[h * S_LEN + rg1] = l1r;
    }
}

// ---------------- pass 2: normalize dumped scores -> weights ---------------
__global__ __launch_bounds__(256) void softmax_norm(float* __restrict__ w) {
    size_t t = (size_t)blockIdx.x * 256 + threadIdx.x;
    size_t e = t * 4;
    int h = (int)(e >> 22);
    int i = (int)((e >> 11) & 2047);
    int j = (int)(e & 2047);
    float4* p = (float4*)(w + e);
    if (j > i) {
        *p = make_float4(0.f, 0.f, 0.f, 0.f);
        return;
    }
    float m = g_m[h * S_LEN + i];
    float inv = 1.0f / g_l[h * S_LEN + i];
    float4 s4 = *p;
    float4 o;
    o.x = __expf(s4.x - m) * inv;
    o.y = (j + 1 <= i) ? __expf(s4.y - m) * inv : 0.f;
    o.z = (j + 2 <= i) ? __expf(s4.z - m) * inv : 0.f;
    o.w = (j + 3 <= i) ? __expf(s4.w - m) * inv : 0.f;
    *p = o;
}

// ---------------- launcher --------------------------------------------------
extern "C" void kernel_launch(void* const* d_in, const int* in_sizes, int n_in,
                              void* d_out, int out_size) {
    const float* hidden = (const float*)d_in[0];
    const int* pos = (const int*)d_in[2];
    const float* Wq = (const float*)d_in[3];
    const float* Wk = (const float*)d_in[4];
    const float* Wv = (const float*)d_in[5];
    const float* Wo = (const float*)d_in[6];

    float *ap;
    cudaGetSymbolAddress((void**)&ap, g_attn);
    __nv_bfloat16 *ah, *al, *wqh, *wql, *wkh, *wkl, *wvh, *wvl, *woh, *wol, *vh, *vl;
    float* vp;
    cudaGetSymbolAddress((void**)&vp, g_V);
    cudaGetSymbolAddress((void**)&ah, g_Ah);
    cudaGetSymbolAddress((void**)&al, g_Al);
    cudaGetSymbolAddress((void**)&wqh, g_WqTh);
    cudaGetSymbolAddress((void**)&wql, g_WqTl);
    cudaGetSymbolAddress((void**)&wkh, g_WkTh);
    cudaGetSymbolAddress((void**)&wkl, g_WkTl);
    cudaGetSymbolAddress((void**)&wvh, g_WvTh);
    cudaGetSymbolAddress((void**)&wvl, g_WvTl);
    cudaGetSymbolAddress((void**)&woh, g_WoTh);
    cudaGetSymbolAddress((void**)&wol, g_WoTl);
    cudaGetSymbolAddress((void**)&vh, g_Vh);
    cudaGetSymbolAddress((void**)&vl, g_Vl);

    float* out = (float*)d_out;
    const long long ATTN_N = (long long)S_LEN * HID_DIM;
    const long long WEI_N = (long long)NH * S_LEN * S_LEN;
    float* obase = nullptr;
    float* wbase = nullptr;
    long long osz = (long long)out_size;
    if (osz >= ATTN_N + WEI_N) { obase = out; wbase = out + ATTN_N; }
    else if (osz == WEI_N)     { wbase = out; }
    else                       { obase = out; }

    cudaFuncSetAttribute(gemm_qkv, cudaFuncAttributeMaxDynamicSharedMemorySize, GEMM_SMEM);
    cudaFuncSetAttribute(gemm_plain, cudaFuncAttributeMaxDynamicSharedMemorySize, GEMM_SMEM);
    cudaFuncSetAttribute(attn_mma, cudaFuncAttributeMaxDynamicSharedMemorySize, ATT_SMEM);

    // prepass
    convert_split<<<(S_LEN * HID_DIM) / 1024, 256>>>(hidden, ah, al, (S_LEN * HID_DIM) / 4);
    transpose_split<<<dim3(HID_DIM / 32, HID_DIM / 32), dim3(32, 8)>>>(Wq, wqh, wql, HID_DIM, HID_DIM);
    transpose_split<<<dim3((NKV * HD) / 32, HID_DIM / 32), dim3(32, 8)>>>(Wk, wkh, wkl, HID_DIM, NKV * HD);
    transpose_split<<<dim3((NKV * HD) / 32, HID_DIM / 32), dim3(32, 8)>>>(Wv, wvh, wvl, HID_DIM, NKV * HD);
    transpose_split<<<dim3(HID_DIM / 32, HID_DIM / 32), dim3(32, 8)>>>(Wo, woh, wol, HID_DIM, HID_DIM);

    // fused QKV projection
    gemm_qkv<<<dim3(48, 16), 256, GEMM_SMEM>>>();

    // rope + l2norm -> bf16 splits; V split
    rope_norm<<<dim3(S_LEN, NH + NKV), 64>>>(pos);
    convert_split<<<(S_LEN * NKV * HD) / 1024, 256>>>(vp, vh, vl, (S_LEN * NKV * HD) / 4);

    // flash attention + raw score dump
    attn_mma<<<512, 256, ATT_SMEM>>>(wbase);

    if (wbase) softmax_norm<<<(unsigned)(WEI_N / 4 / 256), 256>>>(wbase);

    if (obase) {
        convert_split<<<(S_LEN * HID_DIM) / 1024, 256>>>(ap, ah, al, (S_LEN * HID_DIM) / 4);
        gemm_plain<<<dim3(32, 16), 256, GEMM_SMEM>>>(ah, al, woh, wol, obase, HID_DIM, HID_DIM);
    }
}

// round 17
// speedup vs baseline: 4.0468x; 1.4597x over previous
#include <cuda_runtime.h>
#include <cuda_fp16.h>
#include <math.h>
#include <stdint.h>

#define S_LEN 2048
#define HID_DIM 4096
#define NH 32
#define NKV 8
#define HD 128

// ---------------- scratch (device globals; no allocation allowed) ----------
__device__ float g_Q[(size_t)S_LEN * NH * HD];
__device__ float g_K[(size_t)S_LEN * NKV * HD];
__device__ float g_V[(size_t)S_LEN * NKV * HD];
__device__ float g_attn[(size_t)S_LEN * NH * HD];
__device__ float g_m[NH * S_LEN];
__device__ float g_l[NH * S_LEN];

// fp16 buffers: A-operands split (hi/lo), B-operands single
__device__ __half g_Ah[(size_t)S_LEN * HID_DIM];
__device__ __half g_Al[(size_t)S_LEN * HID_DIM];
__device__ __half g_WqT[(size_t)HID_DIM * HID_DIM];     // [N][K]
__device__ __half g_WkT[(size_t)(NKV * HD) * HID_DIM];
__device__ __half g_WvT[(size_t)(NKV * HD) * HID_DIM];
__device__ __half g_WoT[(size_t)HID_DIM * HID_DIM];
__device__ __half g_Qh[(size_t)S_LEN * NH * HD];
__device__ __half g_Ql[(size_t)S_LEN * NH * HD];
__device__ __half g_Kh[(size_t)S_LEN * NKV * HD];
__device__ __half g_Vh[(size_t)S_LEN * NKV * HD];

// ---------------- PTX helpers ----------------------------------------------
__device__ __forceinline__ uint32_t smem_u32(const void* p) {
    uint32_t a;
    asm("{ .reg .u64 t; cvta.to.shared.u64 t, %1; cvt.u32.u64 %0, t; }"
        : "=r"(a) : "l"(p));
    return a;
}
__device__ __forceinline__ void cp_async16(uint32_t dst, const void* src) {
    asm volatile("cp.async.cg.shared.global [%0], [%1], 16;" :: "r"(dst), "l"(src));
}
#define CP_COMMIT() asm volatile("cp.async.commit_group;" ::: "memory")
#define CP_WAIT(n)  asm volatile("cp.async.wait_group %0;" :: "n"(n) : "memory")

__device__ __forceinline__ void ldsm4(uint32_t (&r)[4], uint32_t addr) {
    asm volatile("ldmatrix.sync.aligned.m8n8.x4.shared.b16 {%0,%1,%2,%3}, [%4];"
                 : "=r"(r[0]), "=r"(r[1]), "=r"(r[2]), "=r"(r[3]) : "r"(addr));
}
__device__ __forceinline__ void ldsm4t(uint32_t (&r)[4], uint32_t addr) {
    asm volatile("ldmatrix.sync.aligned.m8n8.x4.trans.shared.b16 {%0,%1,%2,%3}, [%4];"
                 : "=r"(r[0]), "=r"(r[1]), "=r"(r[2]), "=r"(r[3]) : "r"(addr));
}
__device__ __forceinline__ void mma16816(float (&c)[4], const uint32_t (&a)[4],
                                         uint32_t b0, uint32_t b1) {
    asm volatile(
        "mma.sync.aligned.m16n8k16.row.col.f32.f16.f16.f32 "
        "{%0,%1,%2,%3}, {%4,%5,%6,%7}, {%8,%9}, {%0,%1,%2,%3};"
        : "+f"(c[0]), "+f"(c[1]), "+f"(c[2]), "+f"(c[3])
        : "r"(a[0]), "r"(a[1]), "r"(a[2]), "r"(a[3]), "r"(b0), "r"(b1));
}

// ---------------- prepass kernels ------------------------------------------
__global__ __launch_bounds__(256) void convert_split(const float* __restrict__ X,
                                                     __half* __restrict__ H,
                                                     __half* __restrict__ L,
                                                     int n4) {
    int idx = blockIdx.x * 256 + threadIdx.x;
    if (idx >= n4) return;
    float4 v = *(const float4*)(X + (size_t)idx * 4);
    __half h0 = __float2half_rn(v.x), h1 = __float2half_rn(v.y);
    __half h2 = __float2half_rn(v.z), h3 = __float2half_rn(v.w);
    __half l0 = __float2half_rn(v.x - __half2float(h0));
    __half l1 = __float2half_rn(v.y - __half2float(h1));
    __half l2 = __float2half_rn(v.z - __half2float(h2));
    __half l3 = __float2half_rn(v.w - __half2float(h3));
    ((__half2*)H)[idx * 2]     = __halves2half2(h0, h1);
    ((__half2*)H)[idx * 2 + 1] = __halves2half2(h2, h3);
    ((__half2*)L)[idx * 2]     = __halves2half2(l0, l1);
    ((__half2*)L)[idx * 2 + 1] = __halves2half2(l2, l3);
}

__global__ __launch_bounds__(256) void convert_half(const float* __restrict__ X,
                                                    __half* __restrict__ H, int n4) {
    int idx = blockIdx.x * 256 + threadIdx.x;
    if (idx >= n4) return;
    float4 v = *(const float4*)(X + (size_t)idx * 4);
    ((__half2*)H)[idx * 2]     = __halves2half2(__float2half_rn(v.x), __float2half_rn(v.y));
    ((__half2*)H)[idx * 2 + 1] = __halves2half2(__float2half_rn(v.z), __float2half_rn(v.w));
}

// W[K][N] fp32 -> T[N][K] fp16 (transpose, single precision level)
__global__ __launch_bounds__(256) void transpose_half(const float* __restrict__ W,
                                                      __half* __restrict__ T,
                                                      int K, int N) {
    __shared__ float t[32][33];
    int n = blockIdx.x * 32 + threadIdx.x;
    int k0 = blockIdx.y * 32;
    for (int j = threadIdx.y; j < 32; j += 8)
        t[j][threadIdx.x] = W[(size_t)(k0 + j) * N + n];
    __syncthreads();
    int k = k0 + threadIdx.x;
    for (int j = threadIdx.y; j < 32; j += 8) {
        int nn = blockIdx.x * 32 + j;
        T[(size_t)nn * K + k] = __float2half_rn(t[threadIdx.x][j]);
    }
}

// ---------------- fp16x2 GEMM core: C = (Ah+Al) * Bt^T, 2 passes -----------
#define BK 32
#define AST 40
#define MAT_BYTES (128 * AST * 2)
#define STAGE_BYTES (3 * MAT_BYTES)
#define GEMM_SMEM (3 * STAGE_BYTES)

__device__ __forceinline__ void gemm_core(const __half* __restrict__ Ah,
                                          const __half* __restrict__ Al,
                                          const __half* __restrict__ B,
                                          float* __restrict__ C, int N, int K,
                                          int m0, int n0, char* smc) {
    const uint32_t sb = smem_u32(smc);
    const int tid = threadIdx.x, lane = tid & 31, wid = tid >> 5;
    const int wm = wid & 1, wn = wid >> 1;
    const __half* gsrc[3] = { Ah + (size_t)m0 * K, Al + (size_t)m0 * K,
                              B + (size_t)n0 * K };
    const int lrow = tid >> 2, lq = tid & 3;
    const int nch = K / BK;

    float acc[4][4][4];
#pragma unroll
    for (int i = 0; i < 4; i++)
#pragma unroll
        for (int j = 0; j < 4; j++)
#pragma unroll
            for (int q = 0; q < 4; q++) acc[i][j][q] = 0.f;

    // prologue
#pragma unroll
    for (int pc = 0; pc < 2; pc++) {
        uint32_t d0 = sb + pc * STAGE_BYTES;
#pragma unroll
        for (int a = 0; a < 3; a++)
#pragma unroll
            for (int it = 0; it < 2; it++) {
                int r = lrow + it * 64;
                cp_async16(d0 + a * MAT_BYTES + (r * AST + lq * 8) * 2,
                           gsrc[a] + (size_t)r * K + pc * BK + lq * 8);
            }
        CP_COMMIT();
    }

    int st = 0, stw = 2;
    for (int c = 0; c < nch; c++) {
        if (c == nch - 1) { CP_WAIT(0); } else { CP_WAIT(1); }
        __syncthreads();
        if (c + 2 < nch) {
            uint32_t d0 = sb + stw * STAGE_BYTES;
#pragma unroll
            for (int a = 0; a < 3; a++)
#pragma unroll
                for (int it = 0; it < 2; it++) {
                    int r = lrow + it * 64;
                    cp_async16(d0 + a * MAT_BYTES + (r * AST + lq * 8) * 2,
                               gsrc[a] + (size_t)r * K + (c + 2) * BK + lq * 8);
                }
            CP_COMMIT();
        }

        const uint32_t base = sb + st * STAGE_BYTES;
        const int arow = wm * 64 + (lane & 7) + ((lane >> 3) & 1) * 8;
        const int brow = wn * 32 + (lane & 7) + ((lane >> 4) & 1) * 8;
#pragma unroll
        for (int ks = 0; ks < 2; ks++) {
            const int acol = ks * 16 + ((lane >> 4) & 1) * 8;
            const int bcol = ks * 16 + ((lane >> 3) & 1) * 8;
            uint32_t ah[4][4], alr[4][4], bb[2][4];
#pragma unroll
            for (int mt = 0; mt < 4; mt++) {
                uint32_t ad = base + ((arow + mt * 16) * AST + acol) * 2;
                ldsm4(ah[mt], ad);
                ldsm4(alr[mt], ad + MAT_BYTES);
            }
#pragma unroll
            for (int np = 0; np < 2; np++) {
                uint32_t bd = base + 2 * MAT_BYTES + ((brow + np * 16) * AST + bcol) * 2;
                ldsm4(bb[np], bd);
            }
#pragma unroll
            for (int mt = 0; mt < 4; mt++)
#pragma unroll
                for (int nt = 0; nt < 4; nt++) {
                    const int np = nt >> 1, off = (nt & 1) * 2;
                    mma16816(acc[mt][nt], ah[mt], bb[np][off], bb[np][off + 1]);
                    mma16816(acc[mt][nt], alr[mt], bb[np][off], bb[np][off + 1]);
                }
        }
        st = (st == 2) ? 0 : st + 1;
        stw = (stw == 2) ? 0 : stw + 1;
    }

    const int g = lane >> 2, tg = lane & 3;
#pragma unroll
    for (int mt = 0; mt < 4; mt++)
#pragma unroll
        for (int nt = 0; nt < 4; nt++) {
            int gr = m0 + wm * 64 + mt * 16 + g;
            int gc = n0 + wn * 32 + nt * 8 + tg * 2;
            *(float2*)&C[(size_t)gr * N + gc] = make_float2(acc[mt][nt][0], acc[mt][nt][1]);
            *(float2*)&C[(size_t)(gr + 8) * N + gc] = make_float2(acc[mt][nt][2], acc[mt][nt][3]);
        }
}

// fused QKV projection: grid (48, 16); n-tiles 0..31 Q, 32..39 K, 40..47 V
__global__ __launch_bounds__(256) void gemm_qkv() {
    extern __shared__ char smc[];
    const int nt = blockIdx.x, m0 = blockIdx.y * 128;
    const __half* b_;
    float* c_;
    int nOut, n0;
    if (nt < 32)      { b_ = g_WqT; c_ = g_Q; nOut = HID_DIM;  n0 = nt * 128; }
    else if (nt < 40) { b_ = g_WkT; c_ = g_K; nOut = NKV * HD; n0 = (nt - 32) * 128; }
    else              { b_ = g_WvT; c_ = g_V; nOut = NKV * HD; n0 = (nt - 40) * 128; }
    gemm_core(g_Ah, g_Al, b_, c_, nOut, HID_DIM, m0, n0, smc);
}

__global__ __launch_bounds__(256) void gemm_plain(const __half* __restrict__ Ah,
                                                  const __half* __restrict__ Al,
                                                  const __half* __restrict__ B,
                                                  float* __restrict__ C, int N, int K) {
    extern __shared__ char smc[];
    gemm_core(Ah, Al, B, C, N, K, blockIdx.y * 128, blockIdx.x * 128, smc);
}

// ---------------- RoPE + L2 norm -> fp16 (Q split, K single) ---------------
__global__ __launch_bounds__(64) void rope_norm(const int* __restrict__ pos_ids) {
    const int t = blockIdx.x;
    const int hy = blockIdx.y;
    const float* X;
    __half *H, *L = nullptr;
    size_t off;
    if (hy < NH) {
        off = (size_t)t * HID_DIM + hy * HD;
        X = g_Q + off; H = g_Qh + off; L = g_Ql + off;
    } else {
        off = (size_t)t * (NKV * HD) + (hy - NH) * HD;
        X = g_K + off; H = g_Kh + off;
    }

    const int p = threadIdx.x;
    float x0 = X[2 * p], x1 = X[2 * p + 1];
    float pos = (float)pos_ids[t];
    float inv = powf(500000.0f, -((float)(2 * p)) / 128.0f);
    float f = pos * inv;
    float c = cosf(f), s = sinf(f);
    float o0 = x0 * c - x1 * s;
    float o1 = x0 * s + x1 * c;

    float ss = o0 * o0 + o1 * o1;
#pragma unroll
    for (int m = 16; m >= 1; m >>= 1) ss += __shfl_xor_sync(0xffffffffu, ss, m);
    __shared__ float sh[2];
    if ((threadIdx.x & 31) == 0) sh[threadIdx.x >> 5] = ss;
    __syncthreads();
    float tot = sh[0] + sh[1];
    float r = rsqrtf(tot / 128.0f + 1e-6f);
    float q0 = o0 * r, q1 = o1 * r;
    __half h0 = __float2half_rn(q0), h1 = __float2half_rn(q1);
    ((__half2*)H)[p] = __halves2half2(h0, h1);
    if (L)
        ((__half2*)L)[p] = __halves2half2(__float2half_rn(q0 - __half2float(h0)),
                                          __float2half_rn(q1 - __half2float(h1)));
}

// ---------------- Attention: tensor-core flash (fp16x2) --------------------
// Q hi/lo (128x136h each), K single (64x136h), V single (64x136h), P hi/lo (128x72h)
#define QH_O 0
#define QL_O 34816
#define KH_O 69632
#define VH_O 87040
#define PH_O 104448
#define PL_O 122880
#define ATT_SMEM 141312

__global__ __launch_bounds__(256) void attn_mma(float* __restrict__ wptr) {
    extern __shared__ char smc[];
    const uint32_t sb = smem_u32(smc);
    const int tid = threadIdx.x, lane = tid & 31, wid = tid >> 5;
    const int bx = blockIdx.x;
    const int qt = 15 - (bx >> 5);
    const int h = bx & 31;
    const int kh = h >> 2;
    const int q0 = qt * 128;
    const float scale = 0.08838834764831845f;

    // Q tiles (group 1)
    for (int i = tid; i < 4096; i += 256) {
        int mat = i >> 11, r = (i >> 4) & 127, cq = i & 15;
        const __half* s =
            (mat ? g_Ql : g_Qh) + (size_t)(q0 + r) * HID_DIM + h * HD + cq * 8;
        cp_async16(sb + (mat ? QL_O : QH_O) + r * 272 + cq * 16, s);
    }
    CP_COMMIT();

    auto issueK = [&](int k0) {
        for (int i = tid; i < 1024; i += 256) {
            int r = i >> 4, cq = i & 15;
            cp_async16(sb + KH_O + r * 272 + cq * 16,
                       g_Kh + (size_t)(k0 + r) * (NKV * HD) + kh * HD + cq * 8);
        }
        CP_COMMIT();
    };
    auto issueV = [&](int k0) {
        for (int i = tid; i < 1024; i += 256) {
            int r = i >> 4, cq = i & 15;
            cp_async16(sb + VH_O + r * 272 + cq * 16,
                       g_Vh + (size_t)(k0 + r) * (NKV * HD) + kh * HD + cq * 8);
        }
        CP_COMMIT();
    };
    issueK(0);
    issueV(0);

    float o[16][4];
#pragma unroll
    for (int i = 0; i < 16; i++)
#pragma unroll
        for (int q = 0; q < 4; q++) o[i][q] = 0.f;

    const int g = lane >> 2, tg = lane & 3;
    const int rl0 = wid * 16 + g;
    const int rg0 = q0 + rl0, rg1 = rg0 + 8;
    float m0r = -INFINITY, m1r = -INFINITY, l0r = 0.f, l1r = 0.f;

    const int ktEnd = (q0 + 127) >> 6;
    for (int kt = 0; kt <= ktEnd; kt++) {
        const int k0 = kt * 64;
        CP_WAIT(1);
        __syncthreads();

        // ---- S = Q K^T (2-pass: qh*k + ql*k) ----
        float s[8][4];
#pragma unroll
        for (int nt = 0; nt < 8; nt++)
#pragma unroll
            for (int q = 0; q < 4; q++) s[nt][q] = 0.f;

#pragma unroll
        for (int kc = 0; kc < 8; kc++) {
            uint32_t aaddr = sb + QH_O +
                ((wid * 16 + (lane & 15)) * 136 + kc * 16 + (lane >> 4) * 8) * 2;
            uint32_t ah[4], al[4];
            ldsm4(ah, aaddr);
            ldsm4(al, aaddr + (QL_O - QH_O));
            uint32_t bb[4][4];
#pragma unroll
            for (int np = 0; np < 4; np++) {
                uint32_t baddr = sb + KH_O +
                    ((np * 16 + (lane & 7) + ((lane >> 4) & 1) * 8) * 136 +
                     kc * 16 + ((lane >> 3) & 1) * 8) * 2;
                ldsm4(bb[np], baddr);
            }
#pragma unroll
            for (int nt = 0; nt < 8; nt++) {
                const int np = nt >> 1, off = (nt & 1) * 2;
                mma16816(s[nt], ah, bb[np][off], bb[np][off + 1]);
                mma16816(s[nt], al, bb[np][off], bb[np][off + 1]);
            }
        }
        __syncthreads();
        if (kt < ktEnd) issueK(k0 + 64);

        // ---- scale, dump raw, mask, online softmax ----
        float mt0 = -INFINITY, mt1 = -INFINITY;
#pragma unroll
        for (int nt = 0; nt < 8; nt++) {
            s[nt][0] *= scale; s[nt][1] *= scale; s[nt][2] *= scale; s[nt][3] *= scale;
            if (wptr) {
                size_t b0 = ((size_t)h * S_LEN + rg0) * S_LEN + k0 + nt * 8 + tg * 2;
                *(float2*)&wptr[b0] = make_float2(s[nt][0], s[nt][1]);
                *(float2*)&wptr[b0 + (size_t)8 * S_LEN] = make_float2(s[nt][2], s[nt][3]);
            }
            const int c0 = k0 + nt * 8 + tg * 2;
            if (c0 > rg0) s[nt][0] = -INFINITY;
            if (c0 + 1 > rg0) s[nt][1] = -INFINITY;
            if (c0 > rg1) s[nt][2] = -INFINITY;
            if (c0 + 1 > rg1) s[nt][3] = -INFINITY;
            mt0 = fmaxf(mt0, fmaxf(s[nt][0], s[nt][1]));
            mt1 = fmaxf(mt1, fmaxf(s[nt][2], s[nt][3]));
        }
        mt0 = fmaxf(mt0, __shfl_xor_sync(0xffffffffu, mt0, 1));
        mt0 = fmaxf(mt0, __shfl_xor_sync(0xffffffffu, mt0, 2));
        mt1 = fmaxf(mt1, __shfl_xor_sync(0xffffffffu, mt1, 1));
        mt1 = fmaxf(mt1, __shfl_xor_sync(0xffffffffu, mt1, 2));

        const float mn0 = fmaxf(m0r, mt0), mn1 = fmaxf(m1r, mt1);
        const float f0 = __expf(m0r - mn0), f1 = __expf(m1r - mn1);
        m0r = mn0; m1r = mn1;

        float rs0 = 0.f, rs1 = 0.f;
#pragma unroll
        for (int nt = 0; nt < 8; nt++) {
            float p0 = __expf(s[nt][0] - mn0), p1 = __expf(s[nt][1] - mn0);
            float p2 = __expf(s[nt][2] - mn1), p3 = __expf(s[nt][3] - mn1);
            rs0 += p0 + p1;
            rs1 += p2 + p3;
            __half h0 = __float2half_rn(p0), h1 = __float2half_rn(p1);
            __half h2 = __float2half_rn(p2), h3 = __float2half_rn(p3);
            uint32_t po = (rl0 * 72 + nt * 8 + tg * 2) * 2;
            *(__half2*)(smc + PH_O + po) = __halves2half2(h0, h1);
            *(__half2*)(smc + PH_O + po + 8 * 144) = __halves2half2(h2, h3);
            *(__half2*)(smc + PL_O + po) =
                __halves2half2(__float2half_rn(p0 - __half2float(h0)),
                               __float2half_rn(p1 - __half2float(h1)));
            *(__half2*)(smc + PL_O + po + 8 * 144) =
                __halves2half2(__float2half_rn(p2 - __half2float(h2)),
                               __float2half_rn(p3 - __half2float(h3)));
        }
        rs0 += __shfl_xor_sync(0xffffffffu, rs0, 1);
        rs0 += __shfl_xor_sync(0xffffffffu, rs0, 2);
        rs1 += __shfl_xor_sync(0xffffffffu, rs1, 1);
        rs1 += __shfl_xor_sync(0xffffffffu, rs1, 2);
        l0r = l0r * f0 + rs0;
        l1r = l1r * f1 + rs1;
#pragma unroll
        for (int nt = 0; nt < 16; nt++) {
            o[nt][0] *= f0; o[nt][1] *= f0; o[nt][2] *= f1; o[nt][3] *= f1;
        }

        if (kt == ktEnd) { CP_WAIT(0); } else { CP_WAIT(1); }
        __syncwarp();

        // ---- O += P V (2-pass: ph*v + pl*v) ----
#pragma unroll
        for (int kc = 0; kc < 4; kc++) {
            uint32_t paddr = sb + PH_O +
                ((wid * 16 + (lane & 15)) * 72 + kc * 16 + (lane >> 4) * 8) * 2;
            uint32_t ph[4], pl[4];
            ldsm4(ph, paddr);
            ldsm4(pl, paddr + (PL_O - PH_O));
#pragma unroll
            for (int ng = 0; ng < 8; ng++) {
                uint32_t vaddr = sb + VH_O +
                    ((kc * 16 + (lane & 15)) * 136 + ng * 16 + (lane >> 4) * 8) * 2;
                uint32_t dv[4];
                ldsm4t(dv, vaddr);
                mma16816(o[2 * ng],     ph, dv[0], dv[1]);
                mma16816(o[2 * ng + 1], ph, dv[2], dv[3]);
                mma16816(o[2 * ng],     pl, dv[0], dv[1]);
                mma16816(o[2 * ng + 1], pl, dv[2], dv[3]);
            }
        }
        __syncthreads();
        if (kt < ktEnd) issueV(k0 + 64);
    }

    const float inv0 = 1.0f / l0r, inv1 = 1.0f / l1r;
#pragma unroll
    for (int nt = 0; nt < 16; nt++) {
        int col = nt * 8 + tg * 2;
        size_t b0 = (size_t)rg0 * HID_DIM + h * HD + col;
        *(float2*)&g_attn[b0] = make_float2(o[nt][0] * inv0, o[nt][1] * inv0);
        *(float2*)&g_attn[b0 + (size_t)8 * HID_DIM] =
            make_float2(o[nt][2] * inv1, o[nt][3] * inv1);
    }
    if (tg == 0) {
        g_m[h * S_LEN + rg0] = m0r;
        g_l[h * S_LEN + rg0] = l0r;
        g_m[h * S_LEN + rg1] = m1r;
        g_l[h * S_LEN + rg1] = l1r;
    }
}

// ---------------- pass 2: normalize dumped scores -> weights ---------------
__global__ __launch_bounds__(256) void softmax_norm(float* __restrict__ w) {
    size_t t = (size_t)blockIdx.x * 256 + threadIdx.x;
    size_t e = t * 4;
    int h = (int)(e >> 22);
    int i = (int)((e >> 11) & 2047);
    int j = (int)(e & 2047);
    float4* p = (float4*)(w + e);
    if (j > i) {
        *p = make_float4(0.f, 0.f, 0.f, 0.f);
        return;
    }
    float m = g_m[h * S_LEN + i];
    float inv = 1.0f / g_l[h * S_LEN + i];
    float4 s4 = *p;
    float4 o;
    o.x = __expf(s4.x - m) * inv;
    o.y = (j + 1 <= i) ? __expf(s4.y - m) * inv : 0.f;
    o.z = (j + 2 <= i) ? __expf(s4.z - m) * inv : 0.f;
    o.w = (j + 3 <= i) ? __expf(s4.w - m) * inv : 0.f;
    *p = o;
}

// ---------------- launcher --------------------------------------------------
extern "C" void kernel_launch(void* const* d_in, const int* in_sizes, int n_in,
                              void* d_out, int out_size) {
    const float* hidden = (const float*)d_in[0];
    const int* pos = (const int*)d_in[2];
    const float* Wq = (const float*)d_in[3];
    const float* Wk = (const float*)d_in[4];
    const float* Wv = (const float*)d_in[5];
    const float* Wo = (const float*)d_in[6];

    float *ap, *vp;
    cudaGetSymbolAddress((void**)&ap, g_attn);
    cudaGetSymbolAddress((void**)&vp, g_V);
    __half *ah, *al, *wqt, *wkt, *wvt, *wot, *vh;
    cudaGetSymbolAddress((void**)&ah, g_Ah);
    cudaGetSymbolAddress((void**)&al, g_Al);
    cudaGetSymbolAddress((void**)&wqt, g_WqT);
    cudaGetSymbolAddress((void**)&wkt, g_WkT);
    cudaGetSymbolAddress((void**)&wvt, g_WvT);
    cudaGetSymbolAddress((void**)&wot, g_WoT);
    cudaGetSymbolAddress((void**)&vh, g_Vh);

    float* out = (float*)d_out;
    const long long ATTN_N = (long long)S_LEN * HID_DIM;
    const long long WEI_N = (long long)NH * S_LEN * S_LEN;
    float* obase = nullptr;
    float* wbase = nullptr;
    long long osz = (long long)out_size;
    if (osz >= ATTN_N + WEI_N) { obase = out; wbase = out + ATTN_N; }
    else if (osz == WEI_N)     { wbase = out; }
    else                       { obase = out; }

    cudaFuncSetAttribute(gemm_qkv, cudaFuncAttributeMaxDynamicSharedMemorySize, GEMM_SMEM);
    cudaFuncSetAttribute(gemm_plain, cudaFuncAttributeMaxDynamicSharedMemorySize, GEMM_SMEM);
    cudaFuncSetAttribute(attn_mma, cudaFuncAttributeMaxDynamicSharedMemorySize, ATT_SMEM);

    // prepass
    convert_split<<<(S_LEN * HID_DIM) / 1024, 256>>>(hidden, ah, al, (S_LEN * HID_DIM) / 4);
    transpose_half<<<dim3(HID_DIM / 32, HID_DIM / 32), dim3(32, 8)>>>(Wq, wqt, HID_DIM, HID_DIM);
    transpose_half<<<dim3((NKV * HD) / 32, HID_DIM / 32), dim3(32, 8)>>>(Wk, wkt, HID_DIM, NKV * HD);
    transpose_half<<<dim3((NKV * HD) / 32, HID_DIM / 32), dim3(32, 8)>>>(Wv, wvt, HID_DIM, NKV * HD);
    transpose_half<<<dim3(HID_DIM / 32, HID_DIM / 32), dim3(32, 8)>>>(Wo, wot, HID_DIM, HID_DIM);

    // fused QKV projection (fp16x2)
    gemm_qkv<<<dim3(48, 16), 256, GEMM_SMEM>>>();

    // rope + l2norm -> fp16 (Q split, K single); V single
    rope_norm<<<dim3(S_LEN, NH + NKV), 64>>>(pos);
    convert_half<<<(S_LEN * NKV * HD) / 1024, 256>>>(vp, vh, (S_LEN * NKV * HD) / 4);

    // flash attention + raw score dump
    attn_mma<<<512, 256, ATT_SMEM>>>(wbase);

    if (wbase) softmax_norm<<<(unsigned)(WEI_N / 4 / 256), 256>>>(wbase);

    if (obase) {
        convert_split<<<(S_LEN * HID_DIM) / 1024, 256>>>(ap, ah, al, (S_LEN * HID_DIM) / 4);
        gemm_plain<<<dim3(32, 16), 256, GEMM_SMEM>>>(ah, al, wot, obase, HID_DIM, HID_DIM);
    }
}